// round 2
// baseline (speedup 1.0000x reference)
#include <cuda_runtime.h>
#include <cstdint>

#define D_IN 4096
#define N_FEAT 4096
#define BATCH 16384
#define TOPK 128

#define BM 128
#define BN 128
#define BK 16

// ---------------------------------------------------------------------------
// Kernel 1: y = relu((x - pb) @ W + b), written straight into d_out.
// 128x128x16 SIMT fp32 tiled GEMM, 256 threads, 8x8 microtile.
// Accuracy: two-level accumulation — each BK=16 slab is summed into a fresh
// partial register, then folded into the main accumulator. Effective rounding
// chain ~272 instead of 4096 -> ~15x smaller accumulation error, which shrinks
// the top-K boundary-swap count that dominates rel_err.
// ---------------------------------------------------------------------------
__global__ __launch_bounds__(256) void encoder_gemm_relu(
    const float* __restrict__ x,    // [BATCH, D_IN]
    const float* __restrict__ pb,   // [D_IN]
    const float* __restrict__ W,    // [D_IN, N_FEAT] (contraction over dim 0)
    const float* __restrict__ be,   // [N_FEAT]
    float* __restrict__ out)        // [BATCH, N_FEAT]
{
    __shared__ float As[BK][BM];        // transposed: As[k][m]
    __shared__ float Bs[BK][BN];        // Bs[k][n]

    const int tid = threadIdx.x;
    const int tx = tid & 15;            // 0..15 -> n microtile
    const int ty = tid >> 4;            // 0..15 -> m microtile

    const int m0 = blockIdx.y * BM;
    const int n0 = blockIdx.x * BN;

    float acc[8][8];
#pragma unroll
    for (int r = 0; r < 8; r++)
#pragma unroll
        for (int c = 0; c < 8; c++) acc[r][c] = 0.0f;

    // A tile loader mapping: 512 float4 per tile, 2 per thread
    const int a_row0 = tid >> 2;        // 0..63
    const int a_j4   = tid & 3;         // 0..3 (float4 index along k)
    // B tile loader mapping
    const int b_row0 = tid >> 5;        // 0..7
    const int b_j4   = tid & 31;        // 0..31 (float4 index along n)

    for (int k0 = 0; k0 < D_IN; k0 += BK) {
        // ---- load A tile (BM x BK), subtract preencoder bias, store transposed
        const float4 pbv = *reinterpret_cast<const float4*>(pb + k0 + a_j4 * 4);
#pragma unroll
        for (int h = 0; h < 2; h++) {
            const int ar = a_row0 + h * 64;
            const float4 v = *reinterpret_cast<const float4*>(
                x + (size_t)(m0 + ar) * D_IN + k0 + a_j4 * 4);
            As[a_j4 * 4 + 0][ar] = v.x - pbv.x;
            As[a_j4 * 4 + 1][ar] = v.y - pbv.y;
            As[a_j4 * 4 + 2][ar] = v.z - pbv.z;
            As[a_j4 * 4 + 3][ar] = v.w - pbv.w;
        }
        // ---- load B tile (BK x BN) directly
#pragma unroll
        for (int h = 0; h < 2; h++) {
            const int br = b_row0 + h * 8;
            const float4 v = *reinterpret_cast<const float4*>(
                W + (size_t)(k0 + br) * N_FEAT + n0 + b_j4 * 4);
            *reinterpret_cast<float4*>(&Bs[br][b_j4 * 4]) = v;
        }
        __syncthreads();

        // ---- fresh partial accumulators for this BK slab
        float part[8][8];
#pragma unroll
        for (int r = 0; r < 8; r++)
#pragma unroll
            for (int c = 0; c < 8; c++) part[r][c] = 0.0f;

#pragma unroll
        for (int kk = 0; kk < BK; kk++) {
            float a[8], b[8];
            *reinterpret_cast<float4*>(a)     = *reinterpret_cast<const float4*>(&As[kk][ty * 8]);
            *reinterpret_cast<float4*>(a + 4) = *reinterpret_cast<const float4*>(&As[kk][ty * 8 + 4]);
            *reinterpret_cast<float4*>(b)     = *reinterpret_cast<const float4*>(&Bs[kk][tx * 8]);
            *reinterpret_cast<float4*>(b + 4) = *reinterpret_cast<const float4*>(&Bs[kk][tx * 8 + 4]);
#pragma unroll
            for (int r = 0; r < 8; r++)
#pragma unroll
                for (int c = 0; c < 8; c++)
                    part[r][c] = fmaf(a[r], b[c], part[r][c]);
        }

        // ---- fold slab into main accumulator (short second-level chain)
#pragma unroll
        for (int r = 0; r < 8; r++)
#pragma unroll
            for (int c = 0; c < 8; c++)
                acc[r][c] += part[r][c];

        __syncthreads();
    }

    // epilogue: + b_enc, relu, store
    float bv[8];
    *reinterpret_cast<float4*>(bv)     = *reinterpret_cast<const float4*>(be + n0 + tx * 8);
    *reinterpret_cast<float4*>(bv + 4) = *reinterpret_cast<const float4*>(be + n0 + tx * 8 + 4);

#pragma unroll
    for (int r = 0; r < 8; r++) {
        const int m = m0 + ty * 8 + r;
        float4 o0, o1;
        o0.x = fmaxf(acc[r][0] + bv[0], 0.0f);
        o0.y = fmaxf(acc[r][1] + bv[1], 0.0f);
        o0.z = fmaxf(acc[r][2] + bv[2], 0.0f);
        o0.w = fmaxf(acc[r][3] + bv[3], 0.0f);
        o1.x = fmaxf(acc[r][4] + bv[4], 0.0f);
        o1.y = fmaxf(acc[r][5] + bv[5], 0.0f);
        o1.z = fmaxf(acc[r][6] + bv[6], 0.0f);
        o1.w = fmaxf(acc[r][7] + bv[7], 0.0f);
        float4* op = reinterpret_cast<float4*>(out + (size_t)m * N_FEAT + n0 + tx * 8);
        op[0] = o0;
        op[1] = o1;
    }
}

// ---------------------------------------------------------------------------
// Kernel 2: per-row exact k-th-largest (K=128) via 4-pass MSB radix select on
// float bits (valid: all acts >= 0 so uint bit order == float order), then
// in-place mask out[i] = acts[i] * (acts[i] >= thr).
// One CTA (256 threads) per row of 4096 floats.
// ---------------------------------------------------------------------------
__global__ __launch_bounds__(256) void topk_threshold_mask(
    float* __restrict__ out)        // [BATCH, N_FEAT], in-place
{
    __shared__ float    srow[N_FEAT];       // 16 KB
    __shared__ unsigned hist[256];
    __shared__ unsigned hs[256];
    __shared__ unsigned sSel;
    __shared__ unsigned sAbove;

    const int tid = threadIdx.x;
    float* rowp = out + (size_t)blockIdx.x * N_FEAT;

    // load row (vectorized)
#pragma unroll
    for (int i = tid; i < N_FEAT / 4; i += 256) {
        const float4 v = reinterpret_cast<const float4*>(rowp)[i];
        *reinterpret_cast<float4*>(&srow[i * 4]) = v;
    }
    __syncthreads();

    unsigned prefix = 0u;
    unsigned hi_mask = 0u;
    int krem = TOPK;

#pragma unroll
    for (int pass = 0; pass < 4; pass++) {
        const int shift = 24 - 8 * pass;

        hist[tid] = 0u;
        __syncthreads();

#pragma unroll
        for (int i = 0; i < N_FEAT / 256; i++) {
            const unsigned bits = __float_as_uint(srow[tid + i * 256]);
            if ((bits & hi_mask) == prefix) {
                atomicAdd(&hist[(bits >> shift) & 0xFFu], 1u);
            }
        }
        __syncthreads();

        // suffix-inclusive scan: hs[b] = count of matched elements with bucket >= b
        hs[tid] = hist[tid];
        __syncthreads();
        for (int off = 1; off < 256; off <<= 1) {
            const unsigned add = (tid + off < 256) ? hs[tid + off] : 0u;
            __syncthreads();
            hs[tid] += add;
            __syncthreads();
        }

        // unique b with hs[b] >= krem > hs[b+1]
        const unsigned above = (tid == 255) ? 0u : hs[tid + 1];
        if (hs[tid] >= (unsigned)krem && above < (unsigned)krem) {
            sSel = (unsigned)tid;
            sAbove = above;
        }
        __syncthreads();

        prefix |= (sSel << shift);
        hi_mask |= (0xFFu << shift);
        krem -= (int)sAbove;
        __syncthreads();
    }

    const float thr = __uint_as_float(prefix);

    // mask + write back
#pragma unroll
    for (int i = tid; i < N_FEAT / 4; i += 256) {
        float4 v = *reinterpret_cast<const float4*>(&srow[i * 4]);
        v.x = (v.x >= thr) ? v.x : 0.0f;
        v.y = (v.y >= thr) ? v.y : 0.0f;
        v.z = (v.z >= thr) ? v.z : 0.0f;
        v.w = (v.w >= thr) ? v.w : 0.0f;
        reinterpret_cast<float4*>(rowp)[i] = v;
    }
}

// ---------------------------------------------------------------------------
extern "C" void kernel_launch(void* const* d_in, const int* in_sizes, int n_in,
                              void* d_out, int out_size)
{
    const float* x  = (const float*)d_in[0];
    const float* pb = (const float*)d_in[1];
    const float* W  = (const float*)d_in[2];
    const float* be = (const float*)d_in[3];
    float* out = (float*)d_out;

    dim3 grid(N_FEAT / BN, BATCH / BM);   // (32, 128)
    encoder_gemm_relu<<<grid, 256>>>(x, pb, W, be, out);
    topk_threshold_mask<<<BATCH, 256>>>(out);
}

// round 3
// speedup vs baseline: 1.0011x; 1.0011x over previous
#include <cuda_runtime.h>
#include <cstdint>

#define D_IN 4096
#define N_FEAT 4096
#define BATCH 16384
#define TOPK 128

#define BM 128
#define BN 128
#define BK 16

// ---------------------------------------------------------------------------
// Kernel 1: y = relu((x - pb) @ W + b), written straight into d_out.
// 128x128x16 SIMT fp32 tiled GEMM, 256 threads, 8x8 microtile.
// Accuracy: two-level accumulation — each BK=16 slab is summed into a fresh
// partial register, then folded into the main accumulator. Effective rounding
// chain ~272 instead of 4096 -> ~15x smaller accumulation error, which shrinks
// the top-K boundary-swap count that dominates rel_err.
// ---------------------------------------------------------------------------
__global__ __launch_bounds__(256) void encoder_gemm_relu(
    const float* __restrict__ x,    // [BATCH, D_IN]
    const float* __restrict__ pb,   // [D_IN]
    const float* __restrict__ W,    // [D_IN, N_FEAT] (contraction over dim 0)
    const float* __restrict__ be,   // [N_FEAT]
    float* __restrict__ out)        // [BATCH, N_FEAT]
{
    __shared__ float As[BK][BM];        // transposed: As[k][m]
    __shared__ float Bs[BK][BN];        // Bs[k][n]

    const int tid = threadIdx.x;
    const int tx = tid & 15;            // 0..15 -> n microtile
    const int ty = tid >> 4;            // 0..15 -> m microtile

    const int m0 = blockIdx.y * BM;
    const int n0 = blockIdx.x * BN;

    float acc[8][8];
#pragma unroll
    for (int r = 0; r < 8; r++)
#pragma unroll
        for (int c = 0; c < 8; c++) acc[r][c] = 0.0f;

    // A tile loader mapping: 512 float4 per tile, 2 per thread
    const int a_row0 = tid >> 2;        // 0..63
    const int a_j4   = tid & 3;         // 0..3 (float4 index along k)
    // B tile loader mapping
    const int b_row0 = tid >> 5;        // 0..7
    const int b_j4   = tid & 31;        // 0..31 (float4 index along n)

    for (int k0 = 0; k0 < D_IN; k0 += BK) {
        // ---- load A tile (BM x BK), subtract preencoder bias, store transposed
        const float4 pbv = *reinterpret_cast<const float4*>(pb + k0 + a_j4 * 4);
#pragma unroll
        for (int h = 0; h < 2; h++) {
            const int ar = a_row0 + h * 64;
            const float4 v = *reinterpret_cast<const float4*>(
                x + (size_t)(m0 + ar) * D_IN + k0 + a_j4 * 4);
            As[a_j4 * 4 + 0][ar] = v.x - pbv.x;
            As[a_j4 * 4 + 1][ar] = v.y - pbv.y;
            As[a_j4 * 4 + 2][ar] = v.z - pbv.z;
            As[a_j4 * 4 + 3][ar] = v.w - pbv.w;
        }
        // ---- load B tile (BK x BN) directly
#pragma unroll
        for (int h = 0; h < 2; h++) {
            const int br = b_row0 + h * 8;
            const float4 v = *reinterpret_cast<const float4*>(
                W + (size_t)(k0 + br) * N_FEAT + n0 + b_j4 * 4);
            *reinterpret_cast<float4*>(&Bs[br][b_j4 * 4]) = v;
        }
        __syncthreads();

        // ---- fresh partial accumulators for this BK slab
        float part[8][8];
#pragma unroll
        for (int r = 0; r < 8; r++)
#pragma unroll
            for (int c = 0; c < 8; c++) part[r][c] = 0.0f;

#pragma unroll
        for (int kk = 0; kk < BK; kk++) {
            float a[8], b[8];
            *reinterpret_cast<float4*>(a)     = *reinterpret_cast<const float4*>(&As[kk][ty * 8]);
            *reinterpret_cast<float4*>(a + 4) = *reinterpret_cast<const float4*>(&As[kk][ty * 8 + 4]);
            *reinterpret_cast<float4*>(b)     = *reinterpret_cast<const float4*>(&Bs[kk][tx * 8]);
            *reinterpret_cast<float4*>(b + 4) = *reinterpret_cast<const float4*>(&Bs[kk][tx * 8 + 4]);
#pragma unroll
            for (int r = 0; r < 8; r++)
#pragma unroll
                for (int c = 0; c < 8; c++)
                    part[r][c] = fmaf(a[r], b[c], part[r][c]);
        }

        // ---- fold slab into main accumulator (short second-level chain)
#pragma unroll
        for (int r = 0; r < 8; r++)
#pragma unroll
            for (int c = 0; c < 8; c++)
                acc[r][c] += part[r][c];

        __syncthreads();
    }

    // epilogue: + b_enc, relu, store
    float bv[8];
    *reinterpret_cast<float4*>(bv)     = *reinterpret_cast<const float4*>(be + n0 + tx * 8);
    *reinterpret_cast<float4*>(bv + 4) = *reinterpret_cast<const float4*>(be + n0 + tx * 8 + 4);

#pragma unroll
    for (int r = 0; r < 8; r++) {
        const int m = m0 + ty * 8 + r;
        float4 o0, o1;
        o0.x = fmaxf(acc[r][0] + bv[0], 0.0f);
        o0.y = fmaxf(acc[r][1] + bv[1], 0.0f);
        o0.z = fmaxf(acc[r][2] + bv[2], 0.0f);
        o0.w = fmaxf(acc[r][3] + bv[3], 0.0f);
        o1.x = fmaxf(acc[r][4] + bv[4], 0.0f);
        o1.y = fmaxf(acc[r][5] + bv[5], 0.0f);
        o1.z = fmaxf(acc[r][6] + bv[6], 0.0f);
        o1.w = fmaxf(acc[r][7] + bv[7], 0.0f);
        float4* op = reinterpret_cast<float4*>(out + (size_t)m * N_FEAT + n0 + tx * 8);
        op[0] = o0;
        op[1] = o1;
    }
}

// ---------------------------------------------------------------------------
// Kernel 2: per-row exact k-th-largest (K=128) via 4-pass MSB radix select on
// float bits (valid: all acts >= 0 so uint bit order == float order), then
// in-place mask out[i] = acts[i] * (acts[i] >= thr).
// One CTA (256 threads) per row of 4096 floats.
// ---------------------------------------------------------------------------
__global__ __launch_bounds__(256) void topk_threshold_mask(
    float* __restrict__ out)        // [BATCH, N_FEAT], in-place
{
    __shared__ float    srow[N_FEAT];       // 16 KB
    __shared__ unsigned hist[256];
    __shared__ unsigned hs[256];
    __shared__ unsigned sSel;
    __shared__ unsigned sAbove;

    const int tid = threadIdx.x;
    float* rowp = out + (size_t)blockIdx.x * N_FEAT;

    // load row (vectorized)
#pragma unroll
    for (int i = tid; i < N_FEAT / 4; i += 256) {
        const float4 v = reinterpret_cast<const float4*>(rowp)[i];
        *reinterpret_cast<float4*>(&srow[i * 4]) = v;
    }
    __syncthreads();

    unsigned prefix = 0u;
    unsigned hi_mask = 0u;
    int krem = TOPK;

#pragma unroll
    for (int pass = 0; pass < 4; pass++) {
        const int shift = 24 - 8 * pass;

        hist[tid] = 0u;
        __syncthreads();

#pragma unroll
        for (int i = 0; i < N_FEAT / 256; i++) {
            const unsigned bits = __float_as_uint(srow[tid + i * 256]);
            if ((bits & hi_mask) == prefix) {
                atomicAdd(&hist[(bits >> shift) & 0xFFu], 1u);
            }
        }
        __syncthreads();

        // suffix-inclusive scan: hs[b] = count of matched elements with bucket >= b
        hs[tid] = hist[tid];
        __syncthreads();
        for (int off = 1; off < 256; off <<= 1) {
            const unsigned add = (tid + off < 256) ? hs[tid + off] : 0u;
            __syncthreads();
            hs[tid] += add;
            __syncthreads();
        }

        // unique b with hs[b] >= krem > hs[b+1]
        const unsigned above = (tid == 255) ? 0u : hs[tid + 1];
        if (hs[tid] >= (unsigned)krem && above < (unsigned)krem) {
            sSel = (unsigned)tid;
            sAbove = above;
        }
        __syncthreads();

        prefix |= (sSel << shift);
        hi_mask |= (0xFFu << shift);
        krem -= (int)sAbove;
        __syncthreads();
    }

    const float thr = __uint_as_float(prefix);

    // mask + write back
#pragma unroll
    for (int i = tid; i < N_FEAT / 4; i += 256) {
        float4 v = *reinterpret_cast<const float4*>(&srow[i * 4]);
        v.x = (v.x >= thr) ? v.x : 0.0f;
        v.y = (v.y >= thr) ? v.y : 0.0f;
        v.z = (v.z >= thr) ? v.z : 0.0f;
        v.w = (v.w >= thr) ? v.w : 0.0f;
        reinterpret_cast<float4*>(rowp)[i] = v;
    }
}

// ---------------------------------------------------------------------------
extern "C" void kernel_launch(void* const* d_in, const int* in_sizes, int n_in,
                              void* d_out, int out_size)
{
    const float* x  = (const float*)d_in[0];
    const float* pb = (const float*)d_in[1];
    const float* W  = (const float*)d_in[2];
    const float* be = (const float*)d_in[3];
    float* out = (float*)d_out;

    dim3 grid(N_FEAT / BN, BATCH / BM);   // (32, 128)
    encoder_gemm_relu<<<grid, 256>>>(x, pb, W, be, out);
    topk_threshold_mask<<<BATCH, 256>>>(out);
}

// round 5
// speedup vs baseline: 3.6674x; 3.6633x over previous
#include <cuda_runtime.h>
#include <cstdint>

#define D_IN   4096
#define N_FEAT 4096
#define BATCH  16384
#define TOPK   128
#define WCAND  1.2e-2f

// ---------------- device scratch (no allocs allowed) ------------------------
__device__ float g_WT[(size_t)N_FEAT * D_IN];   // W transposed: [n][k] (fixup)
__device__ float g_thr[BATCH];                  // noisy per-row k-th value

// ---------------- helpers ---------------------------------------------------
__device__ __forceinline__ uint32_t smem_u32(const void* p) {
    uint32_t a;
    asm("{ .reg .u64 t; cvta.to.shared.u64 t, %1; cvt.u32.u64 %0, t; }"
        : "=r"(a) : "l"(p));
    return a;
}
__device__ __forceinline__ uint32_t f2tf32(float f) {
    uint32_t u;
    asm("cvt.rna.tf32.f32 %0, %1;" : "=r"(u) : "f"(f));
    return u;
}
__device__ __forceinline__ void mma_tf32(float c[4], const uint32_t a[4],
                                         const uint32_t b[2]) {
    asm volatile(
        "mma.sync.aligned.m16n8k8.row.col.f32.tf32.tf32.f32 "
        "{%0,%1,%2,%3}, {%4,%5,%6,%7}, {%8,%9}, {%0,%1,%2,%3};"
        : "+f"(c[0]), "+f"(c[1]), "+f"(c[2]), "+f"(c[3])
        : "r"(a[0]), "r"(a[1]), "r"(a[2]), "r"(a[3]), "r"(b[0]), "r"(b[1]));
}
#define CP_ASYNC16(dst_u32, src) \
    asm volatile("cp.async.cg.shared.global [%0], [%1], 16;" \
                 :: "r"(dst_u32), "l"(src) : "memory")
#define CP_COMMIT()  asm volatile("cp.async.commit_group;" ::: "memory")
#define CP_WAIT0()   asm volatile("cp.async.wait_group 0;" ::: "memory")

// ---------------- Kernel 0: W[k][n] -> g_WT[n][k] (for fixup) ---------------
__global__ void transpose_w(const float* __restrict__ W) {
    __shared__ float t[32][33];
    const int n0 = blockIdx.x * 32, k0 = blockIdx.y * 32;
#pragma unroll
    for (int j = 0; j < 32; j += 8)
        t[threadIdx.y + j][threadIdx.x] =
            W[(size_t)(k0 + threadIdx.y + j) * N_FEAT + n0 + threadIdx.x];
    __syncthreads();
#pragma unroll
    for (int j = 0; j < 32; j += 8)
        g_WT[(size_t)(n0 + threadIdx.y + j) * D_IN + k0 + threadIdx.x] =
            t[threadIdx.x][threadIdx.y + j];
}

// ---------------- Kernel 1: tf32 mma.sync GEMM + bias + relu ----------------
// Block 128(M) x 256(N) x 32(K), 8 warps (2x4), warp tile 64x64.
// smem: A[2][128][32] swizzled (k ^= (m&7)<<2), B[2][32][256] (n ^= (k&3)<<3).
#define GM_BM 128
#define GM_BN 256
#define GM_BK 32
#define NIT   (D_IN / GM_BK)          // 128
#define A_F   (GM_BM * GM_BK)         // 4096 floats per buffer
#define B_F   (GM_BK * GM_BN)         // 8192 floats per buffer
#define SM_FLOATS (2 * A_F + 2 * B_F) // 24576 floats = 96 KB

__global__ __launch_bounds__(256, 1) void encoder_gemm_tc(
    const float* __restrict__ x, const float* __restrict__ pb,
    const float* __restrict__ W, const float* __restrict__ be,
    float* __restrict__ out)
{
    extern __shared__ float sm[];
    float* Asm = sm;                  // [2][4096]
    float* Bsm = sm + 2 * A_F;        // [2][8192]
    const uint32_t bsm_u32 = smem_u32(Bsm);

    const int tid  = threadIdx.x;
    const int lane = tid & 31, wid = tid >> 5;
    const int wm = wid & 1, wn = wid >> 1;        // warps 2(m) x 4(n)
    const int g2 = lane >> 2, t4 = lane & 3;

    // block swizzle: group 8 m-blocks per n-sweep for L2 reuse
    const int NUM_N = N_FEAT / GM_BN;             // 16
    const int GROUP = 8;
    const int pid = blockIdx.x;
    const int first_m = (pid / (GROUP * NUM_N)) * GROUP;
    const int inner = pid % (GROUP * NUM_N);
    const int bm = first_m + (inner % GROUP);
    const int bn = inner / GROUP;
    const int m0 = bm * GM_BM, n0 = bn * GM_BN;

    // loader mappings
    const int a_k4 = tid & 7;          // float4 along k
    const int a_mr = tid >> 3;         // 0..31 (+32p)
    const int b_kr = tid >> 6;         // 0..3  (+4p)
    const int b_n4 = tid & 63;         // float4 along n

    float acc[4][8][4];
#pragma unroll
    for (int mt = 0; mt < 4; mt++)
#pragma unroll
        for (int nt = 0; nt < 8; nt++)
#pragma unroll
            for (int r = 0; r < 4; r++) acc[mt][nt][r] = 0.0f;

    float4 apre[4];
    float4 pbv;

    // ---- prologue: tile 0 into buffer 0
    {
        const int k0 = 0;
        pbv = *reinterpret_cast<const float4*>(pb + k0 + a_k4 * 4);
#pragma unroll
        for (int p = 0; p < 4; p++)
            apre[p] = *reinterpret_cast<const float4*>(
                x + (size_t)(m0 + a_mr + 32 * p) * D_IN + k0 + a_k4 * 4);
#pragma unroll
        for (int p = 0; p < 8; p++) {
            const int k = b_kr + 4 * p;
            const uint32_t dst = bsm_u32 +
                (uint32_t)(k * GM_BN + ((b_n4 * 4) ^ ((k & 3) * 8))) * 4u;
            CP_ASYNC16(dst, W + (size_t)(k0 + k) * N_FEAT + n0 + b_n4 * 4);
        }
        CP_COMMIT();
#pragma unroll
        for (int p = 0; p < 4; p++) {
            const int m = a_mr + 32 * p;
            float4 v = apre[p];
            float4 w;
            w.x = __uint_as_float(f2tf32(v.x - pbv.x));
            w.y = __uint_as_float(f2tf32(v.y - pbv.y));
            w.z = __uint_as_float(f2tf32(v.z - pbv.z));
            w.w = __uint_as_float(f2tf32(v.w - pbv.w));
            *reinterpret_cast<float4*>(
                Asm + m * GM_BK + ((a_k4 * 4) ^ ((m & 7) * 4))) = w;
        }
        CP_WAIT0();
        __syncthreads();
    }

    // ---- mainloop
    for (int it = 0; it < NIT; ++it) {
        const int cur = it & 1, nxt = cur ^ 1;
        const bool has_next = (it + 1 < NIT);

        if (has_next) {
            const int k0 = (it + 1) * GM_BK;
            pbv = *reinterpret_cast<const float4*>(pb + k0 + a_k4 * 4);
#pragma unroll
            for (int p = 0; p < 4; p++)
                apre[p] = *reinterpret_cast<const float4*>(
                    x + (size_t)(m0 + a_mr + 32 * p) * D_IN + k0 + a_k4 * 4);
#pragma unroll
            for (int p = 0; p < 8; p++) {
                const int k = b_kr + 4 * p;
                const uint32_t dst = bsm_u32 + (uint32_t)(nxt * B_F) * 4u +
                    (uint32_t)(k * GM_BN + ((b_n4 * 4) ^ ((k & 3) * 8))) * 4u;
                CP_ASYNC16(dst, W + (size_t)(k0 + k) * N_FEAT + n0 + b_n4 * 4);
            }
            CP_COMMIT();
        }

        // compute on buffer cur
        {
            const float* Ab = Asm + cur * A_F;
            const float* Bb = Bsm + cur * B_F;
#pragma unroll
            for (int ks = 0; ks < 4; ks++) {
                const int c0 = ks * 8;
                uint32_t af[4][4];
#pragma unroll
                for (int mt = 0; mt < 4; mt++) {
                    const int mr = wm * 64 + mt * 16 + g2;
                    const int kA0 = (c0 + t4) ^ (g2 * 4);
                    const int kA1 = (c0 + t4 + 4) ^ (g2 * 4);
                    af[mt][0] = __float_as_uint(Ab[mr * GM_BK + kA0]);
                    af[mt][1] = __float_as_uint(Ab[(mr + 8) * GM_BK + kA0]);
                    af[mt][2] = __float_as_uint(Ab[mr * GM_BK + kA1]);
                    af[mt][3] = __float_as_uint(Ab[(mr + 8) * GM_BK + kA1]);
                }
                uint32_t bf[8][2];
#pragma unroll
                for (int nt = 0; nt < 8; nt++) {
                    const int nn = (wn * 64 + nt * 8 + g2) ^ (t4 * 8);
                    bf[nt][0] = f2tf32(Bb[(c0 + t4) * GM_BN + nn]);
                    bf[nt][1] = f2tf32(Bb[(c0 + t4 + 4) * GM_BN + nn]);
                }
#pragma unroll
                for (int mt = 0; mt < 4; mt++)
#pragma unroll
                    for (int nt = 0; nt < 8; nt++)
                        mma_tf32(acc[mt][nt], af[mt], bf[nt]);
            }
        }

        if (has_next) {
#pragma unroll
            for (int p = 0; p < 4; p++) {
                const int m = a_mr + 32 * p;
                float4 v = apre[p];
                float4 w;
                w.x = __uint_as_float(f2tf32(v.x - pbv.x));
                w.y = __uint_as_float(f2tf32(v.y - pbv.y));
                w.z = __uint_as_float(f2tf32(v.z - pbv.z));
                w.w = __uint_as_float(f2tf32(v.w - pbv.w));
                *reinterpret_cast<float4*>(
                    Asm + nxt * A_F + m * GM_BK + ((a_k4 * 4) ^ ((m & 7) * 4))) = w;
            }
            CP_WAIT0();
        }
        __syncthreads();
    }

    // ---- epilogue: bias + relu, direct STG.64
#pragma unroll
    for (int mt = 0; mt < 4; mt++) {
        const int r0 = m0 + wm * 64 + mt * 16 + g2;
#pragma unroll
        for (int nt = 0; nt < 8; nt++) {
            const int col = n0 + wn * 64 + nt * 8 + t4 * 2;
            const float2 bv = *reinterpret_cast<const float2*>(be + col);
            float2 o;
            o.x = fmaxf(acc[mt][nt][0] + bv.x, 0.0f);
            o.y = fmaxf(acc[mt][nt][1] + bv.y, 0.0f);
            *reinterpret_cast<float2*>(out + (size_t)r0 * N_FEAT + col) = o;
            o.x = fmaxf(acc[mt][nt][2] + bv.x, 0.0f);
            o.y = fmaxf(acc[mt][nt][3] + bv.y, 0.0f);
            *reinterpret_cast<float2*>(out + (size_t)(r0 + 8) * N_FEAT + col) = o;
        }
    }
}

// ---------------- Kernel 2: noisy k-th largest per row ----------------------
__global__ __launch_bounds__(256) void topk_threshold(const float* __restrict__ out)
{
    __shared__ float    srow[N_FEAT];
    __shared__ unsigned hist[256], hs[256];
    __shared__ unsigned sSel, sAbove;

    const int tid = threadIdx.x;
    const float* rowp = out + (size_t)blockIdx.x * N_FEAT;
#pragma unroll
    for (int i = tid; i < N_FEAT / 4; i += 256)
        *reinterpret_cast<float4*>(&srow[i * 4]) = reinterpret_cast<const float4*>(rowp)[i];
    __syncthreads();

    unsigned prefix = 0u, hi_mask = 0u;
    int krem = TOPK;
#pragma unroll
    for (int pass = 0; pass < 4; pass++) {
        const int shift = 24 - 8 * pass;
        hist[tid] = 0u;
        __syncthreads();
#pragma unroll
        for (int i = 0; i < N_FEAT / 256; i++) {
            const unsigned bits = __float_as_uint(srow[tid + i * 256]);
            if ((bits & hi_mask) == prefix)
                atomicAdd(&hist[(bits >> shift) & 0xFFu], 1u);
        }
        __syncthreads();
        hs[tid] = hist[tid];
        __syncthreads();
        for (int off = 1; off < 256; off <<= 1) {
            const unsigned add = (tid + off < 256) ? hs[tid + off] : 0u;
            __syncthreads();
            hs[tid] += add;
            __syncthreads();
        }
        const unsigned above = (tid == 255) ? 0u : hs[tid + 1];
        if (hs[tid] >= (unsigned)krem && above < (unsigned)krem) { sSel = tid; sAbove = above; }
        __syncthreads();
        prefix |= (sSel << shift);
        hi_mask |= (0xFFu << shift);
        krem -= (int)sAbove;
        __syncthreads();
    }
    if (tid == 0) g_thr[blockIdx.x] = __uint_as_float(prefix);
}

// ---------------- Kernel 3: boundary fixup (R2-exact arithmetic) ------------
__global__ __launch_bounds__(256) void fixup_mask(
    float* __restrict__ out, const float* __restrict__ x,
    const float* __restrict__ pb, const float* __restrict__ be)
{
    __shared__ float xc[D_IN];
    __shared__ float s_part[256];
    __shared__ int   s_cidx[64];
    __shared__ float s_cval[64];
    __shared__ int   sA, sNc;
    __shared__ unsigned s_vbits;

    const int tid = threadIdx.x;
    const int row = blockIdx.x;
    const float thr = g_thr[row];
    float* rowp = out + (size_t)row * N_FEAT;

#pragma unroll
    for (int i = tid; i < D_IN / 4; i += 256) {
        float4 xv = reinterpret_cast<const float4*>(x + (size_t)row * D_IN)[i];
        const float4 pv = reinterpret_cast<const float4*>(pb)[i];
        xv.x -= pv.x; xv.y -= pv.y; xv.z -= pv.z; xv.w -= pv.w;
        *reinterpret_cast<float4*>(&xc[i * 4]) = xv;
    }
    if (tid == 0) { sA = 0; sNc = 0; s_vbits = 0x7F800000u; }
    __syncthreads();

    const float whi = thr + WCAND, wlo = thr - WCAND;

    for (int i = tid; i < N_FEAT; i += 256) {
        const float a = rowp[i];
        if (a > whi) atomicAdd(&sA, 1);
        else if (a >= wlo) {
            const int p = atomicAdd(&sNc, 1);
            if (p < 64) s_cidx[p] = i;
        }
    }
    __syncthreads();

    const int nc = (sNc < 64) ? sNc : 64;
    const int kk = TOPK - sA;

    // exact recompute: 256 slabs of 16 sequential FMAs, folded in slab order —
    // identical to the blocked fp32 GEMM that measured zero boundary swaps.
    for (int c = 0; c < nc; c++) {
        const float* wrow = g_WT + (size_t)s_cidx[c] * D_IN;
        {
            float part = 0.0f;
            const int b = tid * 16;
#pragma unroll
            for (int j = 0; j < 16; j++)
                part = fmaf(xc[b + j], wrow[b + j], part);
            s_part[tid] = part;
        }
        __syncthreads();
        if (tid == 0) {
            float acc = 0.0f;
            for (int s = 0; s < 256; s++) acc += s_part[s];
            s_cval[c] = fmaxf(acc + be[s_cidx[c]], 0.0f);
        }
        __syncthreads();
    }

    if (tid < nc && kk >= 1) {
        const float v = s_cval[tid];
        int g = 0;
        for (int j = 0; j < nc; j++) g += (s_cval[j] > v);
        if (g <= kk - 1) atomicMin(&s_vbits, __float_as_uint(v));
    }
    __syncthreads();

    const bool fallback = (sNc > 64) || (kk > nc) || (kk < 1);
    const float vstar = fallback ? thr : __uint_as_float(s_vbits);

    for (int i = tid; i < N_FEAT; i += 256) {
        const float a = rowp[i];
        float o;
        if (a > whi) o = a;
        else if (a >= wlo) {
            float ex = a; bool found = false;
            for (int c = 0; c < nc; c++)
                if (s_cidx[c] == i) { ex = s_cval[c]; found = true; break; }
            if (found) o = (ex >= vstar) ? ex : 0.0f;
            else       o = (a >= thr) ? a : 0.0f;
        } else o = 0.0f;
        rowp[i] = o;
    }
}

// ---------------------------------------------------------------------------
extern "C" void kernel_launch(void* const* d_in, const int* in_sizes, int n_in,
                              void* d_out, int out_size)
{
    const float* x  = (const float*)d_in[0];
    const float* pb = (const float*)d_in[1];
    const float* W  = (const float*)d_in[2];
    const float* be = (const float*)d_in[3];
    float* out = (float*)d_out;

    cudaFuncSetAttribute(encoder_gemm_tc,
                         cudaFuncAttributeMaxDynamicSharedMemorySize,
                         SM_FLOATS * 4);

    transpose_w<<<dim3(N_FEAT / 32, D_IN / 32), dim3(32, 8)>>>(W);
    const int nblocks = (BATCH / GM_BM) * (N_FEAT / GM_BN);   // 2048
    encoder_gemm_tc<<<nblocks, 256, SM_FLOATS * 4>>>(x, pb, W, be, out);
    topk_threshold<<<BATCH, 256>>>(out);
    fixup_mask<<<BATCH, 256>>>(out, x, pb, be);
}

// round 6
// speedup vs baseline: 5.7633x; 1.5715x over previous
#include <cuda_runtime.h>
#include <cuda_fp16.h>
#include <cstdint>

#define D_IN   4096
#define N_FEAT 4096
#define BATCH  16384
#define TOPK   128
#define WCAND  1.2e-2f

// ---------------- device scratch (no allocs allowed) ------------------------
__device__ float  g_WT[(size_t)N_FEAT * D_IN];    // W^T fp32 [n][k] (exact fixup)
__device__ __half g_Wh[(size_t)D_IN * N_FEAT];    // W fp16  [k][n] (GEMM B)
__device__ __half g_Xh[(size_t)BATCH * D_IN];     // (x-pb) fp16 [m][k] (GEMM A)

// ---------------- helpers ---------------------------------------------------
__device__ __forceinline__ uint32_t smem_u32(const void* p) {
    uint32_t a;
    asm("{ .reg .u64 t; cvta.to.shared.u64 t, %1; cvt.u32.u64 %0, t; }"
        : "=r"(a) : "l"(p));
    return a;
}
__device__ __forceinline__ void mma_f16(float c[4], const uint32_t a[4],
                                        const uint32_t b[2]) {
    asm volatile(
        "mma.sync.aligned.m16n8k16.row.col.f32.f16.f16.f32 "
        "{%0,%1,%2,%3}, {%4,%5,%6,%7}, {%8,%9}, {%0,%1,%2,%3};"
        : "+f"(c[0]), "+f"(c[1]), "+f"(c[2]), "+f"(c[3])
        : "r"(a[0]), "r"(a[1]), "r"(a[2]), "r"(a[3]), "r"(b[0]), "r"(b[1]));
}
#define LDMATRIX_X4(r0, r1, r2, r3, addr) \
    asm volatile("ldmatrix.sync.aligned.m8n8.x4.shared.b16 {%0,%1,%2,%3}, [%4];" \
                 : "=r"(r0), "=r"(r1), "=r"(r2), "=r"(r3) : "r"(addr))
#define LDMATRIX_X4_T(r0, r1, r2, r3, addr) \
    asm volatile("ldmatrix.sync.aligned.m8n8.x4.trans.shared.b16 {%0,%1,%2,%3}, [%4];" \
                 : "=r"(r0), "=r"(r1), "=r"(r2), "=r"(r3) : "r"(addr))
#define CP_ASYNC16(dst_u32, src) \
    asm volatile("cp.async.cg.shared.global [%0], [%1], 16;" \
                 :: "r"(dst_u32), "l"(src) : "memory")
#define CP_COMMIT()  asm volatile("cp.async.commit_group;" ::: "memory")
#define CP_WAIT2()   asm volatile("cp.async.wait_group 2;" ::: "memory")

__device__ __forceinline__ uint32_t h2u(__half2 h) {
    return *reinterpret_cast<uint32_t*>(&h);
}

// ---------------- Prologue 0: x - pb -> fp16 g_Xh ---------------------------
__global__ __launch_bounds__(256) void convert_x(
    const float* __restrict__ x, const float* __restrict__ pb)
{
    const int i4 = blockIdx.x * 256 + threadIdx.x;       // one float4 per thread
    const float4 v = reinterpret_cast<const float4*>(x)[i4];
    const float4 p = reinterpret_cast<const float4*>(pb)[i4 & (D_IN / 4 - 1)];
    uint2 o;
    o.x = h2u(__floats2half2_rn(v.x - p.x, v.y - p.y));
    o.y = h2u(__floats2half2_rn(v.z - p.z, v.w - p.w));
    reinterpret_cast<uint2*>(g_Xh)[i4] = o;
}

// ---------------- Prologue 1: W -> fp16 g_Wh (same layout) ------------------
__global__ __launch_bounds__(256) void convert_wh(const float* __restrict__ W)
{
    const int i4 = blockIdx.x * 256 + threadIdx.x;
    const float4 v = reinterpret_cast<const float4*>(W)[i4];
    uint2 o;
    o.x = h2u(__floats2half2_rn(v.x, v.y));
    o.y = h2u(__floats2half2_rn(v.z, v.w));
    reinterpret_cast<uint2*>(g_Wh)[i4] = o;
}

// ---------------- Prologue 2: W[k][n] -> g_WT[n][k] fp32 (fixup) ------------
__global__ void transpose_w(const float* __restrict__ W) {
    __shared__ float t[32][33];
    const int n0 = blockIdx.x * 32, k0 = blockIdx.y * 32;
#pragma unroll
    for (int j = 0; j < 32; j += 8)
        t[threadIdx.y + j][threadIdx.x] =
            W[(size_t)(k0 + threadIdx.y + j) * N_FEAT + n0 + threadIdx.x];
    __syncthreads();
#pragma unroll
    for (int j = 0; j < 32; j += 8)
        g_WT[(size_t)(n0 + threadIdx.y + j) * D_IN + k0 + threadIdx.x] =
            t[threadIdx.x][threadIdx.y + j];
}

// ---------------- Kernel 1: fp16 mma.sync GEMM + bias + relu ----------------
// Block 128(M) x 256(N) x 32(K), 8 warps (2x4), warp tile 64x64, 4-stage
// cp.async pipeline, ldmatrix fragment loads from XOR-swizzled fp16 smem.
#define GM_BM 128
#define GM_BN 256
#define GM_BK 32
#define NIT   (D_IN / GM_BK)              // 128
#define STG   4
#define A_BYTES (GM_BM * GM_BK * 2)       // 8192
#define B_BYTES (GM_BK * GM_BN * 2)       // 16384
#define SM_BYTES (STG * (A_BYTES + B_BYTES))  // 98304

__global__ __launch_bounds__(256, 1) void encoder_gemm_h(
    const float* __restrict__ be, float* __restrict__ out)
{
    extern __shared__ char sm[];
    const uint32_t smb = smem_u32(sm);
    const uint32_t aB0 = smb;                     // 4 x 8KB A stages
    const uint32_t bB0 = smb + STG * A_BYTES;     // 4 x 16KB B stages

    const int tid  = threadIdx.x;
    const int lane = tid & 31, wid = tid >> 5;
    const int wm = wid & 1, wn = wid >> 1;
    const int g2 = lane >> 2, t4 = lane & 3;

    // block swizzle: 8 m-blocks per group sweep all 16 n-blocks (L2 reuse)
    const int pid = blockIdx.x;
    const int first_m = (pid >> 7) << 3;          // /(8*16) * 8
    const int inner = pid & 127;
    const int m0 = (first_m + (inner & 7)) * GM_BM;
    const int n0 = (inner >> 3) * GM_BN;

    // cp.async mappings
    const int a_m = tid & 127, a_h = tid >> 7;    // A: 2 chunks of 8 fp16
    const int b_k = tid >> 3,  b_c0 = tid & 7;    // B: 4 chunks of 8 fp16

    float acc[4][8][4];
#pragma unroll
    for (int mt = 0; mt < 4; mt++)
#pragma unroll
        for (int nt = 0; nt < 8; nt++)
#pragma unroll
            for (int r = 0; r < 4; r++) acc[mt][nt][r] = 0.0f;

    // tile loader: issue cp.asyncs for k-tile `kt` into stage `s`
    auto issue_tile = [&](int kt, int s) {
        const int k0 = kt * GM_BK;
        const uint32_t aB = aB0 + s * A_BYTES;
        const uint32_t bB = bB0 + s * B_BYTES;
#pragma unroll
        for (int c = 0; c < 2; c++) {
            const int C = a_h * 2 + c;
            const uint32_t dst = aB + a_m * 64 + (((C ^ ((a_m >> 1) & 3)) << 4));
            CP_ASYNC16(dst, g_Xh + (size_t)(m0 + a_m) * D_IN + k0 + C * 8);
        }
#pragma unroll
        for (int p = 0; p < 4; p++) {
            const int cn = b_c0 + 8 * p;
            const uint32_t dst = bB + b_k * 512 + (((cn ^ (b_k & 7)) << 4));
            CP_ASYNC16(dst, g_Wh + (size_t)(k0 + b_k) * N_FEAT + n0 + cn * 8);
        }
    };

    // prologue: stages 0..2
#pragma unroll
    for (int s = 0; s < STG - 1; s++) { issue_tile(s, s); CP_COMMIT(); }

    for (int it = 0; it < NIT; ++it) {
        CP_WAIT2();
        __syncthreads();
        if (it + STG - 1 < NIT) issue_tile(it + STG - 1, (it + STG - 1) & (STG - 1));
        CP_COMMIT();

        const uint32_t aB = aB0 + (it & (STG - 1)) * A_BYTES;
        const uint32_t bB = bB0 + (it & (STG - 1)) * B_BYTES;
#pragma unroll
        for (int ks = 0; ks < 2; ks++) {
            uint32_t af[4][4];
#pragma unroll
            for (int mt = 0; mt < 4; mt++) {
                const int row = wm * 64 + mt * 16 + (lane & 15);
                const int C = ks * 2 + (lane >> 4);
                const uint32_t addr = aB + row * 64 + ((C ^ ((row >> 1) & 3)) << 4);
                LDMATRIX_X4(af[mt][0], af[mt][1], af[mt][2], af[mt][3], addr);
            }
            uint32_t bf[8][2];
#pragma unroll
            for (int q = 0; q < 4; q++) {
                const int j = lane >> 3;
                const int krow = ks * 16 + (j & 1) * 8 + (lane & 7);
                const int chunk = wn * 8 + q * 2 + (j >> 1);
                const uint32_t addr = bB + krow * 512 + ((chunk ^ (krow & 7)) << 4);
                uint32_t r0, r1, r2, r3;
                LDMATRIX_X4_T(r0, r1, r2, r3, addr);
                bf[q * 2][0] = r0; bf[q * 2][1] = r1;
                bf[q * 2 + 1][0] = r2; bf[q * 2 + 1][1] = r3;
            }
#pragma unroll
            for (int mt = 0; mt < 4; mt++)
#pragma unroll
                for (int nt = 0; nt < 8; nt++)
                    mma_f16(acc[mt][nt], af[mt], bf[nt]);
        }
    }

    // epilogue: bias + relu, direct STG.64
#pragma unroll
    for (int mt = 0; mt < 4; mt++) {
        const int r0 = m0 + wm * 64 + mt * 16 + g2;
#pragma unroll
        for (int nt = 0; nt < 8; nt++) {
            const int col = n0 + wn * 64 + nt * 8 + t4 * 2;
            const float2 bv = *reinterpret_cast<const float2*>(be + col);
            float2 o;
            o.x = fmaxf(acc[mt][nt][0] + bv.x, 0.0f);
            o.y = fmaxf(acc[mt][nt][1] + bv.y, 0.0f);
            *reinterpret_cast<float2*>(out + (size_t)r0 * N_FEAT + col) = o;
            o.x = fmaxf(acc[mt][nt][2] + bv.x, 0.0f);
            o.y = fmaxf(acc[mt][nt][3] + bv.y, 0.0f);
            *reinterpret_cast<float2*>(out + (size_t)(r0 + 8) * N_FEAT + col) = o;
        }
    }
}

// ---------------- Kernel 2: merged radix-select + exact fixup + mask --------
// One CTA per row. Row and xc staged once in smem; candidate recompute is
// warp-parallel; the per-candidate fold is bit-identical to the blocked fp32
// GEMM (256 slabs of 16 sequential FMAs, folded in slab order) that measured
// zero boundary swaps vs the reference.
__global__ __launch_bounds__(256) void select_mask(
    float* __restrict__ out, const float* __restrict__ x,
    const float* __restrict__ pb, const float* __restrict__ be)
{
    __shared__ float    srow[N_FEAT];       // 16 KB (noisy acts)
    __shared__ float    xc[D_IN];           // 16 KB (exact fp32 x - pb)
    __shared__ float    sp[8][256];         // 8 KB  (per-warp slab partials)
    __shared__ unsigned hist[256], hs[256];
    __shared__ int      s_cidx[64];
    __shared__ float    s_cval[64];
    __shared__ int      sA, sNc;
    __shared__ unsigned sSel, sAbove, s_vbits;

    const int tid = threadIdx.x;
    const int lane = tid & 31, wid = tid >> 5;
    const int row = blockIdx.x;
    float* rowp = out + (size_t)row * N_FEAT;

#pragma unroll
    for (int i = tid; i < N_FEAT / 4; i += 256)
        *reinterpret_cast<float4*>(&srow[i * 4]) = reinterpret_cast<const float4*>(rowp)[i];
#pragma unroll
    for (int i = tid; i < D_IN / 4; i += 256) {
        float4 xv = reinterpret_cast<const float4*>(x + (size_t)row * D_IN)[i];
        const float4 pv = reinterpret_cast<const float4*>(pb)[i];
        xv.x -= pv.x; xv.y -= pv.y; xv.z -= pv.z; xv.w -= pv.w;
        *reinterpret_cast<float4*>(&xc[i * 4]) = xv;
    }
    if (tid == 0) { sA = 0; sNc = 0; s_vbits = 0x7F800000u; }
    __syncthreads();

    // ---- radix select: noisy k-th largest (acts >= 0 so bit order == order)
    unsigned prefix = 0u, hi_mask = 0u;
    int krem = TOPK;
#pragma unroll
    for (int pass = 0; pass < 4; pass++) {
        const int shift = 24 - 8 * pass;
        hist[tid] = 0u;
        __syncthreads();
#pragma unroll
        for (int i = 0; i < N_FEAT / 256; i++) {
            const unsigned bits = __float_as_uint(srow[tid + i * 256]);
            if ((bits & hi_mask) == prefix)
                atomicAdd(&hist[(bits >> shift) & 0xFFu], 1u);
        }
        __syncthreads();
        hs[tid] = hist[tid];
        __syncthreads();
        for (int off = 1; off < 256; off <<= 1) {
            const unsigned add = (tid + off < 256) ? hs[tid + off] : 0u;
            __syncthreads();
            hs[tid] += add;
            __syncthreads();
        }
        const unsigned above = (tid == 255) ? 0u : hs[tid + 1];
        if (hs[tid] >= (unsigned)krem && above < (unsigned)krem) { sSel = tid; sAbove = above; }
        __syncthreads();
        prefix |= (sSel << shift);
        hi_mask |= (0xFFu << shift);
        krem -= (int)sAbove;
        __syncthreads();
    }
    const float thr = __uint_as_float(prefix);
    const float whi = thr + WCAND, wlo = thr - WCAND;

    // ---- gather boundary candidates
    for (int i = tid; i < N_FEAT; i += 256) {
        const float a = srow[i];
        if (a > whi) atomicAdd(&sA, 1);
        else if (a >= wlo) {
            const int p = atomicAdd(&sNc, 1);
            if (p < 64) s_cidx[p] = i;
        }
    }
    __syncthreads();

    const int nc = (sNc < 64) ? sNc : 64;
    const int kk = TOPK - sA;

    // ---- exact recompute, one candidate per warp
    for (int c = wid; c < nc; c += 8) {
        const float4* w4 = reinterpret_cast<const float4*>(
            g_WT + (size_t)s_cidx[c] * D_IN);
        const float4* x4 = reinterpret_cast<const float4*>(xc);
#pragma unroll
        for (int s8 = 0; s8 < 8; s8++) {
            const int slab = s8 * 32 + lane;          // k = slab*16 .. +15
            float part = 0.0f;
#pragma unroll
            for (int j = 0; j < 4; j++) {
                const float4 a = x4[slab * 4 + j];
                const float4 b = w4[slab * 4 + j];
                part = fmaf(a.x, b.x, part);
                part = fmaf(a.y, b.y, part);
                part = fmaf(a.z, b.z, part);
                part = fmaf(a.w, b.w, part);
            }
            sp[wid][slab] = part;
        }
        __syncwarp();
        if (lane == 0) {
            float acc = 0.0f;
#pragma unroll 8
            for (int j = 0; j < 256; j++) acc += sp[wid][j];   // slab order
            s_cval[c] = fmaxf(acc + be[s_cidx[c]], 0.0f);
        }
        __syncwarp();
    }
    __syncthreads();

    // ---- kk-th largest exact candidate value
    if (tid < nc && kk >= 1) {
        const float v = s_cval[tid];
        int g = 0;
        for (int j = 0; j < nc; j++) g += (s_cval[j] > v);
        if (g <= kk - 1) atomicMin(&s_vbits, __float_as_uint(v));
    }
    __syncthreads();

    const bool fallback = (sNc > 64) || (kk > nc) || (kk < 1);
    const float vstar = fallback ? thr : __uint_as_float(s_vbits);

    // ---- final mask, single global write
    for (int i = tid; i < N_FEAT; i += 256) {
        const float a = srow[i];
        float o;
        if (a > whi) o = a;
        else if (a >= wlo) {
            float ex = a; bool found = false;
            for (int c = 0; c < nc; c++)
                if (s_cidx[c] == i) { ex = s_cval[c]; found = true; break; }
            if (found) o = (ex >= vstar) ? ex : 0.0f;
            else       o = (a >= thr) ? a : 0.0f;
        } else o = 0.0f;
        rowp[i] = o;
    }
}

// ---------------------------------------------------------------------------
extern "C" void kernel_launch(void* const* d_in, const int* in_sizes, int n_in,
                              void* d_out, int out_size)
{
    const float* x  = (const float*)d_in[0];
    const float* pb = (const float*)d_in[1];
    const float* W  = (const float*)d_in[2];
    const float* be = (const float*)d_in[3];
    float* out = (float*)d_out;

    cudaFuncSetAttribute(encoder_gemm_h,
                         cudaFuncAttributeMaxDynamicSharedMemorySize, SM_BYTES);

    convert_x<<<(BATCH * D_IN / 4) / 256, 256>>>(x, pb);
    convert_wh<<<(D_IN * N_FEAT / 4) / 256, 256>>>(W);
    transpose_w<<<dim3(N_FEAT / 32, D_IN / 32), dim3(32, 8)>>>(W);
    encoder_gemm_h<<<(BATCH / GM_BM) * (N_FEAT / GM_BN), 256, SM_BYTES>>>(be, out);
    select_mask<<<BATCH, 256>>>(out, x, pb, be);
}

// round 7
// speedup vs baseline: 5.7790x; 1.0027x over previous
#include <cuda_runtime.h>
#include <cuda_fp16.h>
#include <cstdint>

#define D_IN   4096
#define N_FEAT 4096
#define BATCH  16384
#define TOPK   128
#define WCAND  1.2e-2f

// ---------------- device scratch (no allocs allowed) ------------------------
__device__ float  g_WT[(size_t)N_FEAT * D_IN];    // W^T fp32 [n][k] (exact fixup)
__device__ __half g_Wh[(size_t)D_IN * N_FEAT];    // W fp16  [k][n] (GEMM B)
__device__ __half g_Xh[(size_t)BATCH * D_IN];     // (x-pb) fp16 [m][k] (GEMM A)

// ---------------- helpers ---------------------------------------------------
__device__ __forceinline__ uint32_t smem_u32(const void* p) {
    uint32_t a;
    asm("{ .reg .u64 t; cvta.to.shared.u64 t, %1; cvt.u32.u64 %0, t; }"
        : "=r"(a) : "l"(p));
    return a;
}
__device__ __forceinline__ void mma_f16(float c[4], const uint32_t a[4],
                                        const uint32_t b[2]) {
    asm volatile(
        "mma.sync.aligned.m16n8k16.row.col.f32.f16.f16.f32 "
        "{%0,%1,%2,%3}, {%4,%5,%6,%7}, {%8,%9}, {%0,%1,%2,%3};"
        : "+f"(c[0]), "+f"(c[1]), "+f"(c[2]), "+f"(c[3])
        : "r"(a[0]), "r"(a[1]), "r"(a[2]), "r"(a[3]), "r"(b[0]), "r"(b[1]));
}
#define LDMATRIX_X4(r0, r1, r2, r3, addr) \
    asm volatile("ldmatrix.sync.aligned.m8n8.x4.shared.b16 {%0,%1,%2,%3}, [%4];" \
                 : "=r"(r0), "=r"(r1), "=r"(r2), "=r"(r3) : "r"(addr))
#define LDMATRIX_X4_T(r0, r1, r2, r3, addr) \
    asm volatile("ldmatrix.sync.aligned.m8n8.x4.trans.shared.b16 {%0,%1,%2,%3}, [%4];" \
                 : "=r"(r0), "=r"(r1), "=r"(r2), "=r"(r3) : "r"(addr))
#define CP_ASYNC16(dst_u32, src) \
    asm volatile("cp.async.cg.shared.global [%0], [%1], 16;" \
                 :: "r"(dst_u32), "l"(src) : "memory")
#define CP_COMMIT()  asm volatile("cp.async.commit_group;" ::: "memory")
#define CP_WAIT2()   asm volatile("cp.async.wait_group 2;" ::: "memory")

__device__ __forceinline__ uint32_t h2u(__half2 h) {
    return *reinterpret_cast<uint32_t*>(&h);
}

// ---------------- Prologue 0: x - pb -> fp16 g_Xh ---------------------------
__global__ __launch_bounds__(256) void convert_x(
    const float* __restrict__ x, const float* __restrict__ pb)
{
    const int i4 = blockIdx.x * 256 + threadIdx.x;       // one float4 per thread
    const float4 v = reinterpret_cast<const float4*>(x)[i4];
    const float4 p = reinterpret_cast<const float4*>(pb)[i4 & (D_IN / 4 - 1)];
    uint2 o;
    o.x = h2u(__floats2half2_rn(v.x - p.x, v.y - p.y));
    o.y = h2u(__floats2half2_rn(v.z - p.z, v.w - p.w));
    reinterpret_cast<uint2*>(g_Xh)[i4] = o;
}

// ---------------- Prologue 1: W -> fp16 g_Wh (same layout) ------------------
__global__ __launch_bounds__(256) void convert_wh(const float* __restrict__ W)
{
    const int i4 = blockIdx.x * 256 + threadIdx.x;
    const float4 v = reinterpret_cast<const float4*>(W)[i4];
    uint2 o;
    o.x = h2u(__floats2half2_rn(v.x, v.y));
    o.y = h2u(__floats2half2_rn(v.z, v.w));
    reinterpret_cast<uint2*>(g_Wh)[i4] = o;
}

// ---------------- Prologue 2: W[k][n] -> g_WT[n][k] fp32 (fixup) ------------
__global__ void transpose_w(const float* __restrict__ W) {
    __shared__ float t[32][33];
    const int n0 = blockIdx.x * 32, k0 = blockIdx.y * 32;
#pragma unroll
    for (int j = 0; j < 32; j += 8)
        t[threadIdx.y + j][threadIdx.x] =
            W[(size_t)(k0 + threadIdx.y + j) * N_FEAT + n0 + threadIdx.x];
    __syncthreads();
#pragma unroll
    for (int j = 0; j < 32; j += 8)
        g_WT[(size_t)(n0 + threadIdx.y + j) * D_IN + k0 + threadIdx.x] =
            t[threadIdx.x][threadIdx.y + j];
}

// ---------------- Kernel 1: fp16 mma.sync GEMM + bias + relu ----------------
// Block 128(M) x 256(N) x 32(K), 8 warps (2x4), warp tile 64x64, 4-stage
// cp.async pipeline, ldmatrix fragment loads from XOR-swizzled fp16 smem.
#define GM_BM 128
#define GM_BN 256
#define GM_BK 32
#define NIT   (D_IN / GM_BK)              // 128
#define STG   4
#define A_BYTES (GM_BM * GM_BK * 2)       // 8192
#define B_BYTES (GM_BK * GM_BN * 2)       // 16384
#define SM_BYTES (STG * (A_BYTES + B_BYTES))  // 98304

__global__ __launch_bounds__(256, 1) void encoder_gemm_h(
    const float* __restrict__ be, float* __restrict__ out)
{
    extern __shared__ char sm[];
    const uint32_t smb = smem_u32(sm);
    const uint32_t aB0 = smb;                     // 4 x 8KB A stages
    const uint32_t bB0 = smb + STG * A_BYTES;     // 4 x 16KB B stages

    const int tid  = threadIdx.x;
    const int lane = tid & 31, wid = tid >> 5;
    const int wm = wid & 1, wn = wid >> 1;
    const int g2 = lane >> 2, t4 = lane & 3;

    // block swizzle: 8 m-blocks per group sweep all 16 n-blocks (L2 reuse)
    const int pid = blockIdx.x;
    const int first_m = (pid >> 7) << 3;          // /(8*16) * 8
    const int inner = pid & 127;
    const int m0 = (first_m + (inner & 7)) * GM_BM;
    const int n0 = (inner >> 3) * GM_BN;

    // cp.async mappings
    const int a_m = tid & 127, a_h = tid >> 7;    // A: 2 chunks of 8 fp16
    const int b_k = tid >> 3,  b_c0 = tid & 7;    // B: 4 chunks of 8 fp16

    float acc[4][8][4];
#pragma unroll
    for (int mt = 0; mt < 4; mt++)
#pragma unroll
        for (int nt = 0; nt < 8; nt++)
#pragma unroll
            for (int r = 0; r < 4; r++) acc[mt][nt][r] = 0.0f;

    // tile loader: issue cp.asyncs for k-tile `kt` into stage `s`
    auto issue_tile = [&](int kt, int s) {
        const int k0 = kt * GM_BK;
        const uint32_t aB = aB0 + s * A_BYTES;
        const uint32_t bB = bB0 + s * B_BYTES;
#pragma unroll
        for (int c = 0; c < 2; c++) {
            const int C = a_h * 2 + c;
            const uint32_t dst = aB + a_m * 64 + (((C ^ ((a_m >> 1) & 3)) << 4));
            CP_ASYNC16(dst, g_Xh + (size_t)(m0 + a_m) * D_IN + k0 + C * 8);
        }
#pragma unroll
        for (int p = 0; p < 4; p++) {
            const int cn = b_c0 + 8 * p;
            const uint32_t dst = bB + b_k * 512 + (((cn ^ (b_k & 7)) << 4));
            CP_ASYNC16(dst, g_Wh + (size_t)(k0 + b_k) * N_FEAT + n0 + cn * 8);
        }
    };

    // prologue: stages 0..2
#pragma unroll
    for (int s = 0; s < STG - 1; s++) { issue_tile(s, s); CP_COMMIT(); }

    for (int it = 0; it < NIT; ++it) {
        CP_WAIT2();
        __syncthreads();
        if (it + STG - 1 < NIT) issue_tile(it + STG - 1, (it + STG - 1) & (STG - 1));
        CP_COMMIT();

        const uint32_t aB = aB0 + (it & (STG - 1)) * A_BYTES;
        const uint32_t bB = bB0 + (it & (STG - 1)) * B_BYTES;
#pragma unroll
        for (int ks = 0; ks < 2; ks++) {
            uint32_t af[4][4];
#pragma unroll
            for (int mt = 0; mt < 4; mt++) {
                const int row = wm * 64 + mt * 16 + (lane & 15);
                const int C = ks * 2 + (lane >> 4);
                const uint32_t addr = aB + row * 64 + ((C ^ ((row >> 1) & 3)) << 4);
                LDMATRIX_X4(af[mt][0], af[mt][1], af[mt][2], af[mt][3], addr);
            }
            uint32_t bf[8][2];
#pragma unroll
            for (int q = 0; q < 4; q++) {
                const int j = lane >> 3;
                const int krow = ks * 16 + (j & 1) * 8 + (lane & 7);
                const int chunk = wn * 8 + q * 2 + (j >> 1);
                const uint32_t addr = bB + krow * 512 + ((chunk ^ (krow & 7)) << 4);
                uint32_t r0, r1, r2, r3;
                LDMATRIX_X4_T(r0, r1, r2, r3, addr);
                bf[q * 2][0] = r0; bf[q * 2][1] = r1;
                bf[q * 2 + 1][0] = r2; bf[q * 2 + 1][1] = r3;
            }
#pragma unroll
            for (int mt = 0; mt < 4; mt++)
#pragma unroll
                for (int nt = 0; nt < 8; nt++)
                    mma_f16(acc[mt][nt], af[mt], bf[nt]);
        }
    }

    // epilogue: bias + relu, direct STG.64
#pragma unroll
    for (int mt = 0; mt < 4; mt++) {
        const int r0 = m0 + wm * 64 + mt * 16 + g2;
#pragma unroll
        for (int nt = 0; nt < 8; nt++) {
            const int col = n0 + wn * 64 + nt * 8 + t4 * 2;
            const float2 bv = *reinterpret_cast<const float2*>(be + col);
            float2 o;
            o.x = fmaxf(acc[mt][nt][0] + bv.x, 0.0f);
            o.y = fmaxf(acc[mt][nt][1] + bv.y, 0.0f);
            *reinterpret_cast<float2*>(out + (size_t)r0 * N_FEAT + col) = o;
            o.x = fmaxf(acc[mt][nt][2] + bv.x, 0.0f);
            o.y = fmaxf(acc[mt][nt][3] + bv.y, 0.0f);
            *reinterpret_cast<float2*>(out + (size_t)(r0 + 8) * N_FEAT + col) = o;
        }
    }
}

// ---------------- Kernel 2: merged radix-select + exact fixup + mask --------
// One CTA per row. Row and xc staged once in smem; candidate recompute is
// warp-parallel; the per-candidate fold is bit-identical to the blocked fp32
// GEMM (256 slabs of 16 sequential FMAs, folded in slab order) that measured
// zero boundary swaps vs the reference.
__global__ __launch_bounds__(256) void select_mask(
    float* __restrict__ out, const float* __restrict__ x,
    const float* __restrict__ pb, const float* __restrict__ be)
{
    __shared__ float    srow[N_FEAT];       // 16 KB (noisy acts)
    __shared__ float    xc[D_IN];           // 16 KB (exact fp32 x - pb)
    __shared__ float    sp[8][256];         // 8 KB  (per-warp slab partials)
    __shared__ unsigned hist[256], hs[256];
    __shared__ int      s_cidx[64];
    __shared__ float    s_cval[64];
    __shared__ int      sA, sNc;
    __shared__ unsigned sSel, sAbove, s_vbits;

    const int tid = threadIdx.x;
    const int lane = tid & 31, wid = tid >> 5;
    const int row = blockIdx.x;
    float* rowp = out + (size_t)row * N_FEAT;

#pragma unroll
    for (int i = tid; i < N_FEAT / 4; i += 256)
        *reinterpret_cast<float4*>(&srow[i * 4]) = reinterpret_cast<const float4*>(rowp)[i];
#pragma unroll
    for (int i = tid; i < D_IN / 4; i += 256) {
        float4 xv = reinterpret_cast<const float4*>(x + (size_t)row * D_IN)[i];
        const float4 pv = reinterpret_cast<const float4*>(pb)[i];
        xv.x -= pv.x; xv.y -= pv.y; xv.z -= pv.z; xv.w -= pv.w;
        *reinterpret_cast<float4*>(&xc[i * 4]) = xv;
    }
    if (tid == 0) { sA = 0; sNc = 0; s_vbits = 0x7F800000u; }
    __syncthreads();

    // ---- radix select: noisy k-th largest (acts >= 0 so bit order == order)
    unsigned prefix = 0u, hi_mask = 0u;
    int krem = TOPK;
#pragma unroll
    for (int pass = 0; pass < 4; pass++) {
        const int shift = 24 - 8 * pass;
        hist[tid] = 0u;
        __syncthreads();
#pragma unroll
        for (int i = 0; i < N_FEAT / 256; i++) {
            const unsigned bits = __float_as_uint(srow[tid + i * 256]);
            if ((bits & hi_mask) == prefix)
                atomicAdd(&hist[(bits >> shift) & 0xFFu], 1u);
        }
        __syncthreads();
        hs[tid] = hist[tid];
        __syncthreads();
        for (int off = 1; off < 256; off <<= 1) {
            const unsigned add = (tid + off < 256) ? hs[tid + off] : 0u;
            __syncthreads();
            hs[tid] += add;
            __syncthreads();
        }
        const unsigned above = (tid == 255) ? 0u : hs[tid + 1];
        if (hs[tid] >= (unsigned)krem && above < (unsigned)krem) { sSel = tid; sAbove = above; }
        __syncthreads();
        prefix |= (sSel << shift);
        hi_mask |= (0xFFu << shift);
        krem -= (int)sAbove;
        __syncthreads();
    }
    const float thr = __uint_as_float(prefix);
    const float whi = thr + WCAND, wlo = thr - WCAND;

    // ---- gather boundary candidates
    for (int i = tid; i < N_FEAT; i += 256) {
        const float a = srow[i];
        if (a > whi) atomicAdd(&sA, 1);
        else if (a >= wlo) {
            const int p = atomicAdd(&sNc, 1);
            if (p < 64) s_cidx[p] = i;
        }
    }
    __syncthreads();

    const int nc = (sNc < 64) ? sNc : 64;
    const int kk = TOPK - sA;

    // ---- exact recompute, one candidate per warp
    for (int c = wid; c < nc; c += 8) {
        const float4* w4 = reinterpret_cast<const float4*>(
            g_WT + (size_t)s_cidx[c] * D_IN);
        const float4* x4 = reinterpret_cast<const float4*>(xc);
#pragma unroll
        for (int s8 = 0; s8 < 8; s8++) {
            const int slab = s8 * 32 + lane;          // k = slab*16 .. +15
            float part = 0.0f;
#pragma unroll
            for (int j = 0; j < 4; j++) {
                const float4 a = x4[slab * 4 + j];
                const float4 b = w4[slab * 4 + j];
                part = fmaf(a.x, b.x, part);
                part = fmaf(a.y, b.y, part);
                part = fmaf(a.z, b.z, part);
                part = fmaf(a.w, b.w, part);
            }
            sp[wid][slab] = part;
        }
        __syncwarp();
        if (lane == 0) {
            float acc = 0.0f;
#pragma unroll 8
            for (int j = 0; j < 256; j++) acc += sp[wid][j];   // slab order
            s_cval[c] = fmaxf(acc + be[s_cidx[c]], 0.0f);
        }
        __syncwarp();
    }
    __syncthreads();

    // ---- kk-th largest exact candidate value
    if (tid < nc && kk >= 1) {
        const float v = s_cval[tid];
        int g = 0;
        for (int j = 0; j < nc; j++) g += (s_cval[j] > v);
        if (g <= kk - 1) atomicMin(&s_vbits, __float_as_uint(v));
    }
    __syncthreads();

    const bool fallback = (sNc > 64) || (kk > nc) || (kk < 1);
    const float vstar = fallback ? thr : __uint_as_float(s_vbits);

    // ---- final mask, single global write
    for (int i = tid; i < N_FEAT; i += 256) {
        const float a = srow[i];
        float o;
        if (a > whi) o = a;
        else if (a >= wlo) {
            float ex = a; bool found = false;
            for (int c = 0; c < nc; c++)
                if (s_cidx[c] == i) { ex = s_cval[c]; found = true; break; }
            if (found) o = (ex >= vstar) ? ex : 0.0f;
            else       o = (a >= thr) ? a : 0.0f;
        } else o = 0.0f;
        rowp[i] = o;
    }
}

// ---------------------------------------------------------------------------
extern "C" void kernel_launch(void* const* d_in, const int* in_sizes, int n_in,
                              void* d_out, int out_size)
{
    const float* x  = (const float*)d_in[0];
    const float* pb = (const float*)d_in[1];
    const float* W  = (const float*)d_in[2];
    const float* be = (const float*)d_in[3];
    float* out = (float*)d_out;

    cudaFuncSetAttribute(encoder_gemm_h,
                         cudaFuncAttributeMaxDynamicSharedMemorySize, SM_BYTES);

    convert_x<<<(BATCH * D_IN / 4) / 256, 256>>>(x, pb);
    convert_wh<<<(D_IN * N_FEAT / 4) / 256, 256>>>(W);
    transpose_w<<<dim3(N_FEAT / 32, D_IN / 32), dim3(32, 8)>>>(W);
    encoder_gemm_h<<<(BATCH / GM_BM) * (N_FEAT / GM_BN), 256, SM_BYTES>>>(be, out);
    select_mask<<<BATCH, 256>>>(out, x, pb, be);
}

// round 8
// speedup vs baseline: 7.3226x; 1.2671x over previous
#include <cuda_runtime.h>
#include <cuda_fp16.h>
#include <cstdint>

#define D_IN   4096
#define N_FEAT 4096
#define BATCH  16384
#define TOPK   128
#define WCAND  1.2e-2f

// ---------------- device scratch (no allocs allowed) ------------------------
__device__ float  g_WT[(size_t)N_FEAT * D_IN];    // W^T fp32 [n][k] (exact fixup)
__device__ __half g_Wh[(size_t)D_IN * N_FEAT];    // W fp16  [k][n] (GEMM B)
__device__ __half g_Xh[(size_t)BATCH * D_IN];     // (x-pb) fp16 [m][k] (GEMM A)

// ---------------- helpers ---------------------------------------------------
__device__ __forceinline__ uint32_t smem_u32(const void* p) {
    uint32_t a;
    asm("{ .reg .u64 t; cvta.to.shared.u64 t, %1; cvt.u32.u64 %0, t; }"
        : "=r"(a) : "l"(p));
    return a;
}
__device__ __forceinline__ void mma_f16(float c[4], const uint32_t a[4],
                                        const uint32_t b[2]) {
    asm volatile(
        "mma.sync.aligned.m16n8k16.row.col.f32.f16.f16.f32 "
        "{%0,%1,%2,%3}, {%4,%5,%6,%7}, {%8,%9}, {%0,%1,%2,%3};"
        : "+f"(c[0]), "+f"(c[1]), "+f"(c[2]), "+f"(c[3])
        : "r"(a[0]), "r"(a[1]), "r"(a[2]), "r"(a[3]), "r"(b[0]), "r"(b[1]));
}
#define LDMATRIX_X4(r0, r1, r2, r3, addr) \
    asm volatile("ldmatrix.sync.aligned.m8n8.x4.shared.b16 {%0,%1,%2,%3}, [%4];" \
                 : "=r"(r0), "=r"(r1), "=r"(r2), "=r"(r3) : "r"(addr))
#define LDMATRIX_X4_T(r0, r1, r2, r3, addr) \
    asm volatile("ldmatrix.sync.aligned.m8n8.x4.trans.shared.b16 {%0,%1,%2,%3}, [%4];" \
                 : "=r"(r0), "=r"(r1), "=r"(r2), "=r"(r3) : "r"(addr))
#define CP_ASYNC16(dst_u32, src) \
    asm volatile("cp.async.cg.shared.global [%0], [%1], 16;" \
                 :: "r"(dst_u32), "l"(src) : "memory")
#define CP_COMMIT()  asm volatile("cp.async.commit_group;" ::: "memory")
#define CP_WAIT2()   asm volatile("cp.async.wait_group 2;" ::: "memory")

__device__ __forceinline__ uint32_t h2u(__half2 h) {
    return *reinterpret_cast<uint32_t*>(&h);
}

// ---------------- Prologue 0: x - pb -> fp16 g_Xh ---------------------------
__global__ __launch_bounds__(256) void convert_x(
    const float* __restrict__ x, const float* __restrict__ pb)
{
    const int i4 = blockIdx.x * 256 + threadIdx.x;
    const float4 v = reinterpret_cast<const float4*>(x)[i4];
    const float4 p = reinterpret_cast<const float4*>(pb)[i4 & (D_IN / 4 - 1)];
    uint2 o;
    o.x = h2u(__floats2half2_rn(v.x - p.x, v.y - p.y));
    o.y = h2u(__floats2half2_rn(v.z - p.z, v.w - p.w));
    reinterpret_cast<uint2*>(g_Xh)[i4] = o;
}

// ---------------- Prologue 1: W -> fp16 g_Wh --------------------------------
__global__ __launch_bounds__(256) void convert_wh(const float* __restrict__ W)
{
    const int i4 = blockIdx.x * 256 + threadIdx.x;
    const float4 v = reinterpret_cast<const float4*>(W)[i4];
    uint2 o;
    o.x = h2u(__floats2half2_rn(v.x, v.y));
    o.y = h2u(__floats2half2_rn(v.z, v.w));
    reinterpret_cast<uint2*>(g_Wh)[i4] = o;
}

// ---------------- Prologue 2: W[k][n] -> g_WT[n][k] fp32 (fixup) ------------
__global__ void transpose_w(const float* __restrict__ W) {
    __shared__ float t[32][33];
    const int n0 = blockIdx.x * 32, k0 = blockIdx.y * 32;
#pragma unroll
    for (int j = 0; j < 32; j += 8)
        t[threadIdx.y + j][threadIdx.x] =
            W[(size_t)(k0 + threadIdx.y + j) * N_FEAT + n0 + threadIdx.x];
    __syncthreads();
#pragma unroll
    for (int j = 0; j < 32; j += 8)
        g_WT[(size_t)(n0 + threadIdx.y + j) * D_IN + k0 + threadIdx.x] =
            t[threadIdx.x][threadIdx.y + j];
}

// ---------------- Kernel 1: fp16 mma.sync GEMM + bias + relu ----------------
// Block 128(M) x 256(N) x 32(K), 16 warps (4x4), warp tile 32x64, 4-stage
// cp.async pipeline. 4 warps per SMSP hide ldmatrix/sync latency.
#define GM_BM 128
#define GM_BN 256
#define GM_BK 32
#define NIT   (D_IN / GM_BK)              // 128
#define STG   4
#define A_BYTES (GM_BM * GM_BK * 2)       // 8192
#define B_BYTES (GM_BK * GM_BN * 2)       // 16384
#define SM_BYTES (STG * (A_BYTES + B_BYTES))  // 98304

__global__ __launch_bounds__(512, 1) void encoder_gemm_h(
    const float* __restrict__ be, float* __restrict__ out)
{
    extern __shared__ char sm[];
    const uint32_t smb = smem_u32(sm);
    const uint32_t aB0 = smb;
    const uint32_t bB0 = smb + STG * A_BYTES;

    const int tid  = threadIdx.x;
    const int lane = tid & 31, wid = tid >> 5;
    const int wm = wid & 3, wn = wid >> 2;        // 4(m) x 4(n) warps
    const int g2 = lane >> 2, t4 = lane & 3;

    // block swizzle: 8 m-blocks per group sweep all 16 n-blocks (L2 reuse)
    const int pid = blockIdx.x;
    const int first_m = (pid >> 7) << 3;
    const int inner = pid & 127;
    const int m0 = (first_m + (inner & 7)) * GM_BM;
    const int n0 = (inner >> 3) * GM_BN;

    // cp.async mappings (512 threads)
    const int a_m = tid >> 2, a_c = tid & 3;      // A: 1 chunk of 8 fp16
    const int b_k = tid >> 4, b_c0 = tid & 15;    // B: 2 chunks of 8 fp16

    // incremental source pointers (advance by GM_BK in k per tile)
    const __half* srcA = g_Xh + (size_t)(m0 + a_m) * D_IN + a_c * 8;
    const __half* srcB = g_Wh + (size_t)b_k * N_FEAT + n0 + b_c0 * 8;

    // precomputed swizzled smem destinations (stage-relative)
    const uint32_t dstA = aB0 + a_m * 64 + ((a_c ^ ((a_m >> 1) & 3)) << 4);
    uint32_t dstB[2];
#pragma unroll
    for (int p = 0; p < 2; p++) {
        const int cn = b_c0 + 16 * p;
        dstB[p] = bB0 + b_k * 512 + ((cn ^ (b_k & 7)) << 4);
    }

    float acc[2][8][4];
#pragma unroll
    for (int mt = 0; mt < 2; mt++)
#pragma unroll
        for (int nt = 0; nt < 8; nt++)
#pragma unroll
            for (int r = 0; r < 4; r++) acc[mt][nt][r] = 0.0f;

    auto issue_tile = [&](int s) {
        const uint32_t off = (uint32_t)s;
        CP_ASYNC16(dstA + off * A_BYTES, srcA);
        CP_ASYNC16(dstB[0] + off * B_BYTES, srcB);
        CP_ASYNC16(dstB[1] + off * B_BYTES, srcB + 128);
        srcA += GM_BK;
        srcB += (size_t)GM_BK * N_FEAT;
    };

#pragma unroll
    for (int s = 0; s < STG - 1; s++) { issue_tile(s); CP_COMMIT(); }

    for (int it = 0; it < NIT; ++it) {
        CP_WAIT2();
        __syncthreads();
        if (it + STG - 1 < NIT) issue_tile((it + STG - 1) & (STG - 1));
        CP_COMMIT();

        const uint32_t aB = aB0 + (it & (STG - 1)) * A_BYTES;
        const uint32_t bB = bB0 + (it & (STG - 1)) * B_BYTES;
#pragma unroll
        for (int ks = 0; ks < 2; ks++) {
            uint32_t af[2][4];
#pragma unroll
            for (int mt = 0; mt < 2; mt++) {
                const int row = wm * 32 + mt * 16 + (lane & 15);
                const int C = ks * 2 + (lane >> 4);
                const uint32_t addr = aB + row * 64 + ((C ^ ((row >> 1) & 3)) << 4);
                LDMATRIX_X4(af[mt][0], af[mt][1], af[mt][2], af[mt][3], addr);
            }
            uint32_t bf[8][2];
#pragma unroll
            for (int q = 0; q < 4; q++) {
                const int j = lane >> 3;
                const int krow = ks * 16 + (j & 1) * 8 + (lane & 7);
                const int chunk = wn * 8 + q * 2 + (j >> 1);
                const uint32_t addr = bB + krow * 512 + ((chunk ^ (krow & 7)) << 4);
                uint32_t r0, r1, r2, r3;
                LDMATRIX_X4_T(r0, r1, r2, r3, addr);
                bf[q * 2][0] = r0; bf[q * 2][1] = r1;
                bf[q * 2 + 1][0] = r2; bf[q * 2 + 1][1] = r3;
            }
#pragma unroll
            for (int mt = 0; mt < 2; mt++)
#pragma unroll
                for (int nt = 0; nt < 8; nt++)
                    mma_f16(acc[mt][nt], af[mt], bf[nt]);
        }
    }

    // epilogue: bias + relu, direct STG.64
#pragma unroll
    for (int mt = 0; mt < 2; mt++) {
        const int r0 = m0 + wm * 32 + mt * 16 + g2;
#pragma unroll
        for (int nt = 0; nt < 8; nt++) {
            const int col = n0 + wn * 64 + nt * 8 + t4 * 2;
            const float2 bv = *reinterpret_cast<const float2*>(be + col);
            float2 o;
            o.x = fmaxf(acc[mt][nt][0] + bv.x, 0.0f);
            o.y = fmaxf(acc[mt][nt][1] + bv.y, 0.0f);
            *reinterpret_cast<float2*>(out + (size_t)r0 * N_FEAT + col) = o;
            o.x = fmaxf(acc[mt][nt][2] + bv.x, 0.0f);
            o.y = fmaxf(acc[mt][nt][3] + bv.y, 0.0f);
            *reinterpret_cast<float2*>(out + (size_t)(r0 + 8) * N_FEAT + col) = o;
        }
    }
}

// ---------------- Kernel 2: merged radix-select + exact fixup + mask --------
__global__ __launch_bounds__(256) void select_mask(
    float* __restrict__ out, const float* __restrict__ x,
    const float* __restrict__ pb, const float* __restrict__ be)
{
    __shared__ float    srow[N_FEAT];
    __shared__ float    xc[D_IN];
    __shared__ float    sp[8][256];
    __shared__ unsigned hist[256], hs[256];
    __shared__ int      s_cidx[64];
    __shared__ float    s_cval[64];
    __shared__ int      sA, sNc;
    __shared__ unsigned sSel, sAbove, s_vbits;

    const int tid = threadIdx.x;
    const int lane = tid & 31, wid = tid >> 5;
    const int row = blockIdx.x;
    float* rowp = out + (size_t)row * N_FEAT;

#pragma unroll
    for (int i = tid; i < N_FEAT / 4; i += 256)
        *reinterpret_cast<float4*>(&srow[i * 4]) = reinterpret_cast<const float4*>(rowp)[i];
#pragma unroll
    for (int i = tid; i < D_IN / 4; i += 256) {
        float4 xv = reinterpret_cast<const float4*>(x + (size_t)row * D_IN)[i];
        const float4 pv = reinterpret_cast<const float4*>(pb)[i];
        xv.x -= pv.x; xv.y -= pv.y; xv.z -= pv.z; xv.w -= pv.w;
        *reinterpret_cast<float4*>(&xc[i * 4]) = xv;
    }
    if (tid == 0) { sA = 0; sNc = 0; s_vbits = 0x7F800000u; }
    __syncthreads();

    // radix select: noisy k-th largest
    unsigned prefix = 0u, hi_mask = 0u;
    int krem = TOPK;
#pragma unroll
    for (int pass = 0; pass < 4; pass++) {
        const int shift = 24 - 8 * pass;
        hist[tid] = 0u;
        __syncthreads();
#pragma unroll
        for (int i = 0; i < N_FEAT / 256; i++) {
            const unsigned bits = __float_as_uint(srow[tid + i * 256]);
            if ((bits & hi_mask) == prefix)
                atomicAdd(&hist[(bits >> shift) & 0xFFu], 1u);
        }
        __syncthreads();
        hs[tid] = hist[tid];
        __syncthreads();
        for (int off = 1; off < 256; off <<= 1) {
            const unsigned add = (tid + off < 256) ? hs[tid + off] : 0u;
            __syncthreads();
            hs[tid] += add;
            __syncthreads();
        }
        const unsigned above = (tid == 255) ? 0u : hs[tid + 1];
        if (hs[tid] >= (unsigned)krem && above < (unsigned)krem) { sSel = tid; sAbove = above; }
        __syncthreads();
        prefix |= (sSel << shift);
        hi_mask |= (0xFFu << shift);
        krem -= (int)sAbove;
        __syncthreads();
    }
    const float thr = __uint_as_float(prefix);
    const float whi = thr + WCAND, wlo = thr - WCAND;

    for (int i = tid; i < N_FEAT; i += 256) {
        const float a = srow[i];
        if (a > whi) atomicAdd(&sA, 1);
        else if (a >= wlo) {
            const int p = atomicAdd(&sNc, 1);
            if (p < 64) s_cidx[p] = i;
        }
    }
    __syncthreads();

    const int nc = (sNc < 64) ? sNc : 64;
    const int kk = TOPK - sA;

    // exact recompute, one candidate per warp; fold bit-identical to the
    // blocked fp32 GEMM (256 slabs of 16 sequential FMAs, slab order).
    for (int c = wid; c < nc; c += 8) {
        const float4* w4 = reinterpret_cast<const float4*>(
            g_WT + (size_t)s_cidx[c] * D_IN);
        const float4* x4 = reinterpret_cast<const float4*>(xc);
#pragma unroll
        for (int s8 = 0; s8 < 8; s8++) {
            const int slab = s8 * 32 + lane;
            float part = 0.0f;
#pragma unroll
            for (int j = 0; j < 4; j++) {
                const float4 a = x4[slab * 4 + j];
                const float4 b = w4[slab * 4 + j];
                part = fmaf(a.x, b.x, part);
                part = fmaf(a.y, b.y, part);
                part = fmaf(a.z, b.z, part);
                part = fmaf(a.w, b.w, part);
            }
            sp[wid][slab] = part;
        }
        __syncwarp();
        if (lane == 0) {
            float acc = 0.0f;
#pragma unroll 8
            for (int j = 0; j < 256; j++) acc += sp[wid][j];
            s_cval[c] = fmaxf(acc + be[s_cidx[c]], 0.0f);
        }
        __syncwarp();
    }
    __syncthreads();

    if (tid < nc && kk >= 1) {
        const float v = s_cval[tid];
        int g = 0;
        for (int j = 0; j < nc; j++) g += (s_cval[j] > v);
        if (g <= kk - 1) atomicMin(&s_vbits, __float_as_uint(v));
    }
    __syncthreads();

    const bool fallback = (sNc > 64) || (kk > nc) || (kk < 1);
    const float vstar = fallback ? thr : __uint_as_float(s_vbits);

    for (int i = tid; i < N_FEAT; i += 256) {
        const float a = srow[i];
        float o;
        if (a > whi) o = a;
        else if (a >= wlo) {
            float ex = a; bool found = false;
            for (int c = 0; c < nc; c++)
                if (s_cidx[c] == i) { ex = s_cval[c]; found = true; break; }
            if (found) o = (ex >= vstar) ? ex : 0.0f;
            else       o = (a >= thr) ? a : 0.0f;
        } else o = 0.0f;
        rowp[i] = o;
    }
}

// ---------------------------------------------------------------------------
extern "C" void kernel_launch(void* const* d_in, const int* in_sizes, int n_in,
                              void* d_out, int out_size)
{
    const float* x  = (const float*)d_in[0];
    const float* pb = (const float*)d_in[1];
    const float* W  = (const float*)d_in[2];
    const float* be = (const float*)d_in[3];
    float* out = (float*)d_out;

    cudaFuncSetAttribute(encoder_gemm_h,
                         cudaFuncAttributeMaxDynamicSharedMemorySize, SM_BYTES);

    convert_x<<<(BATCH * D_IN / 4) / 256, 256>>>(x, pb);
    convert_wh<<<(D_IN * N_FEAT / 4) / 256, 256>>>(W);
    transpose_w<<<dim3(N_FEAT / 32, D_IN / 32), dim3(32, 8)>>>(W);
    encoder_gemm_h<<<(BATCH / GM_BM) * (N_FEAT / GM_BN), 512, SM_BYTES>>>(be, out);
    select_mask<<<BATCH, 256>>>(out, x, pb, be);
}

// round 9
// speedup vs baseline: 7.6172x; 1.0402x over previous
#include <cuda_runtime.h>
#include <cuda_fp16.h>
#include <cstdint>

#define D_IN   4096
#define N_FEAT 4096
#define BATCH  16384
#define TOPK   128
#define WCAND  1.2e-2f

// ---------------- device scratch (no allocs allowed) ------------------------
__device__ float  g_WT[(size_t)N_FEAT * D_IN];    // W^T fp32 [n][k] (exact fixup)
__device__ __half g_Wh[(size_t)D_IN * N_FEAT];    // W fp16  [k][n] (GEMM B)
__device__ __half g_Xh[(size_t)BATCH * D_IN];     // (x-pb) fp16 [m][k] (GEMM A)

// ---------------- helpers ---------------------------------------------------
__device__ __forceinline__ uint32_t smem_u32(const void* p) {
    uint32_t a;
    asm("{ .reg .u64 t; cvta.to.shared.u64 t, %1; cvt.u32.u64 %0, t; }"
        : "=r"(a) : "l"(p));
    return a;
}
__device__ __forceinline__ void mma_f16(float c[4], const uint32_t a[4],
                                        const uint32_t b[2]) {
    asm volatile(
        "mma.sync.aligned.m16n8k16.row.col.f32.f16.f16.f32 "
        "{%0,%1,%2,%3}, {%4,%5,%6,%7}, {%8,%9}, {%0,%1,%2,%3};"
        : "+f"(c[0]), "+f"(c[1]), "+f"(c[2]), "+f"(c[3])
        : "r"(a[0]), "r"(a[1]), "r"(a[2]), "r"(a[3]), "r"(b[0]), "r"(b[1]));
}
#define LDMATRIX_X4(r0, r1, r2, r3, addr) \
    asm volatile("ldmatrix.sync.aligned.m8n8.x4.shared.b16 {%0,%1,%2,%3}, [%4];" \
                 : "=r"(r0), "=r"(r1), "=r"(r2), "=r"(r3) : "r"(addr))
#define LDMATRIX_X4_T(r0, r1, r2, r3, addr) \
    asm volatile("ldmatrix.sync.aligned.m8n8.x4.trans.shared.b16 {%0,%1,%2,%3}, [%4];" \
                 : "=r"(r0), "=r"(r1), "=r"(r2), "=r"(r3) : "r"(addr))
#define CP_ASYNC16(dst_u32, src) \
    asm volatile("cp.async.cg.shared.global [%0], [%1], 16;" \
                 :: "r"(dst_u32), "l"(src) : "memory")
#define CP_COMMIT()  asm volatile("cp.async.commit_group;" ::: "memory")
#define CP_WAIT2()   asm volatile("cp.async.wait_group 2;" ::: "memory")

__device__ __forceinline__ uint32_t h2u(__half2 h) {
    return *reinterpret_cast<uint32_t*>(&h);
}

// ---------------- Prologue 0: x - pb -> fp16 g_Xh ---------------------------
__global__ __launch_bounds__(256) void convert_x(
    const float* __restrict__ x, const float* __restrict__ pb)
{
    const int i4 = blockIdx.x * 256 + threadIdx.x;
    const float4 v = reinterpret_cast<const float4*>(x)[i4];
    const float4 p = reinterpret_cast<const float4*>(pb)[i4 & (D_IN / 4 - 1)];
    uint2 o;
    o.x = h2u(__floats2half2_rn(v.x - p.x, v.y - p.y));
    o.y = h2u(__floats2half2_rn(v.z - p.z, v.w - p.w));
    reinterpret_cast<uint2*>(g_Xh)[i4] = o;
}

// ---------------- Prologue 1: W -> g_WT (fp32, transposed) + g_Wh (fp16) ----
__global__ void prep_w(const float* __restrict__ W) {
    __shared__ float t[32][33];
    const int n0 = blockIdx.x * 32, k0 = blockIdx.y * 32;
#pragma unroll
    for (int j = 0; j < 32; j += 8) {
        const int k = k0 + threadIdx.y + j;
        const float v = W[(size_t)k * N_FEAT + n0 + threadIdx.x];
        t[threadIdx.y + j][threadIdx.x] = v;
        g_Wh[(size_t)k * N_FEAT + n0 + threadIdx.x] = __float2half_rn(v);
    }
    __syncthreads();
#pragma unroll
    for (int j = 0; j < 32; j += 8)
        g_WT[(size_t)(n0 + threadIdx.y + j) * D_IN + k0 + threadIdx.x] =
            t[threadIdx.x][threadIdx.y + j];
}

// ---------------- Kernel 1: fp16 mma.sync GEMM + bias + relu ----------------
// Block 128(M) x 128(N) x 32(K), 8 warps (4m x 2n), warp tile 32x64, 4-stage
// cp.async pipeline, 64KB smem -> 2 CTAs/SM (RF-limited at 128 regs/thread).
#define GM_BM 128
#define GM_BN 128
#define GM_BK 32
#define NIT   (D_IN / GM_BK)              // 128
#define STG   4
#define A_BYTES (GM_BM * GM_BK * 2)       // 8192
#define B_BYTES (GM_BK * GM_BN * 2)       // 8192
#define SM_BYTES (STG * (A_BYTES + B_BYTES))  // 65536

__global__ __launch_bounds__(256, 2) void encoder_gemm_h(
    const float* __restrict__ be, float* __restrict__ out)
{
    extern __shared__ char sm[];
    const uint32_t smb = smem_u32(sm);
    const uint32_t aB0 = smb;
    const uint32_t bB0 = smb + STG * A_BYTES;

    const int tid  = threadIdx.x;
    const int lane = tid & 31, wid = tid >> 5;
    const int wm = wid & 3, wn = wid >> 2;        // 4(m) x 2(n) warps
    const int g2 = lane >> 2, t4 = lane & 3;

    // block swizzle: 8 m-blocks per group sweep all 32 n-blocks (L2 reuse)
    const int pid = blockIdx.x;
    const int first_m = (pid >> 8) << 3;          // /(8*32) * 8
    const int inner = pid & 255;
    const int m0 = (first_m + (inner & 7)) * GM_BM;
    const int n0 = (inner >> 3) * GM_BN;

    // cp.async mappings (256 threads, 2 chunks A + 2 chunks B each)
    const int a_m = tid >> 1, a_c0 = (tid & 1) * 2;   // A: rows 0..127, chunks 0..3
    const int b_k = tid >> 3, b_c0 = tid & 7;         // B: rows 0..31, chunks 0..15

    const __half* srcA = g_Xh + (size_t)(m0 + a_m) * D_IN + a_c0 * 8;
    const __half* srcB = g_Wh + (size_t)b_k * N_FEAT + n0 + b_c0 * 8;

    uint32_t dstA[2], dstB[2];
#pragma unroll
    for (int c = 0; c < 2; c++) {
        const int cc = a_c0 + c;
        dstA[c] = aB0 + a_m * 64 + ((cc ^ ((a_m >> 1) & 3)) << 4);
    }
#pragma unroll
    for (int p = 0; p < 2; p++) {
        const int cn = b_c0 + 8 * p;
        dstB[p] = bB0 + b_k * 256 + ((cn ^ (b_k & 7)) << 4);
    }

    float acc[2][8][4];
#pragma unroll
    for (int mt = 0; mt < 2; mt++)
#pragma unroll
        for (int nt = 0; nt < 8; nt++)
#pragma unroll
            for (int r = 0; r < 4; r++) acc[mt][nt][r] = 0.0f;

    auto issue_tile = [&](int s) {
        CP_ASYNC16(dstA[0] + s * A_BYTES, srcA);
        CP_ASYNC16(dstA[1] + s * A_BYTES, srcA + 8);
        CP_ASYNC16(dstB[0] + s * B_BYTES, srcB);
        CP_ASYNC16(dstB[1] + s * B_BYTES, srcB + 64);
        srcA += GM_BK;
        srcB += (size_t)GM_BK * N_FEAT;
    };

#pragma unroll
    for (int s = 0; s < STG - 1; s++) { issue_tile(s); CP_COMMIT(); }

    for (int it = 0; it < NIT; ++it) {
        CP_WAIT2();
        __syncthreads();
        if (it + STG - 1 < NIT) issue_tile((it + STG - 1) & (STG - 1));
        CP_COMMIT();

        const uint32_t aB = aB0 + (it & (STG - 1)) * A_BYTES;
        const uint32_t bB = bB0 + (it & (STG - 1)) * B_BYTES;
#pragma unroll
        for (int ks = 0; ks < 2; ks++) {
            uint32_t af[2][4];
#pragma unroll
            for (int mt = 0; mt < 2; mt++) {
                const int row = wm * 32 + mt * 16 + (lane & 15);
                const int C = ks * 2 + (lane >> 4);
                const uint32_t addr = aB + row * 64 + ((C ^ ((row >> 1) & 3)) << 4);
                LDMATRIX_X4(af[mt][0], af[mt][1], af[mt][2], af[mt][3], addr);
            }
            uint32_t bf[8][2];
#pragma unroll
            for (int q = 0; q < 4; q++) {
                const int j = lane >> 3;
                const int krow = ks * 16 + (j & 1) * 8 + (lane & 7);
                const int chunk = wn * 8 + q * 2 + (j >> 1);
                const uint32_t addr = bB + krow * 256 + ((chunk ^ (krow & 7)) << 4);
                uint32_t r0, r1, r2, r3;
                LDMATRIX_X4_T(r0, r1, r2, r3, addr);
                bf[q * 2][0] = r0; bf[q * 2][1] = r1;
                bf[q * 2 + 1][0] = r2; bf[q * 2 + 1][1] = r3;
            }
#pragma unroll
            for (int mt = 0; mt < 2; mt++)
#pragma unroll
                for (int nt = 0; nt < 8; nt++)
                    mma_f16(acc[mt][nt], af[mt], bf[nt]);
        }
    }

    // epilogue: bias + relu, direct STG.64
#pragma unroll
    for (int mt = 0; mt < 2; mt++) {
        const int r0 = m0 + wm * 32 + mt * 16 + g2;
#pragma unroll
        for (int nt = 0; nt < 8; nt++) {
            const int col = n0 + wn * 64 + nt * 8 + t4 * 2;
            const float2 bv = *reinterpret_cast<const float2*>(be + col);
            float2 o;
            o.x = fmaxf(acc[mt][nt][0] + bv.x, 0.0f);
            o.y = fmaxf(acc[mt][nt][1] + bv.y, 0.0f);
            *reinterpret_cast<float2*>(out + (size_t)r0 * N_FEAT + col) = o;
            o.x = fmaxf(acc[mt][nt][2] + bv.x, 0.0f);
            o.y = fmaxf(acc[mt][nt][3] + bv.y, 0.0f);
            *reinterpret_cast<float2*>(out + (size_t)(r0 + 8) * N_FEAT + col) = o;
        }
    }
}

// ---------------- Kernel 2: merged radix-select + exact fixup + mask --------
// 512 threads/row. 3-pass radix (24-bit prefix; truncation <= 2.4e-4 << WCAND)
// with warp-shuffle suffix scans. Exact recompute bit-identical to the blocked
// fp32 GEMM (256 slabs of 16 sequential FMAs, folded in slab order).
__global__ __launch_bounds__(512) void select_mask(
    float* __restrict__ out, const float* __restrict__ x,
    const float* __restrict__ pb, const float* __restrict__ be)
{
    __shared__ float    srow[N_FEAT];       // 16 KB
    __shared__ float    xc[D_IN];           // 16 KB
    __shared__ float    sp[8][256];         // 8 KB
    __shared__ unsigned hist[256], hs[256]; // 2 KB
    __shared__ unsigned wsum[8];
    __shared__ int      s_cidx[64];
    __shared__ float    s_cval[64];
    __shared__ int      sA, sNc;
    __shared__ unsigned sSel, sAbove, s_vbits;

    const int tid = threadIdx.x;
    const int lane = tid & 31, wid = tid >> 5;
    const int row = blockIdx.x;
    float* rowp = out + (size_t)row * N_FEAT;

#pragma unroll
    for (int i = tid; i < N_FEAT / 4; i += 512)
        *reinterpret_cast<float4*>(&srow[i * 4]) = reinterpret_cast<const float4*>(rowp)[i];
#pragma unroll
    for (int i = tid; i < D_IN / 4; i += 512) {
        float4 xv = reinterpret_cast<const float4*>(x + (size_t)row * D_IN)[i];
        const float4 pv = reinterpret_cast<const float4*>(pb)[i];
        xv.x -= pv.x; xv.y -= pv.y; xv.z -= pv.z; xv.w -= pv.w;
        *reinterpret_cast<float4*>(&xc[i * 4]) = xv;
    }
    if (tid == 0) { sA = 0; sNc = 0; s_vbits = 0x7F800000u; }
    __syncthreads();

    // ---- 3-pass radix select (acts >= 0 so uint order == float order)
    unsigned prefix = 0u, hi_mask = 0u;
    int krem = TOPK;
#pragma unroll
    for (int pass = 0; pass < 3; pass++) {
        const int shift = 24 - 8 * pass;
        if (tid < 256) hist[tid] = 0u;
        __syncthreads();
#pragma unroll
        for (int i = 0; i < N_FEAT / 512; i++) {
            const unsigned bits = __float_as_uint(srow[tid + i * 512]);
            if ((bits & hi_mask) == prefix)
                atomicAdd(&hist[(bits >> shift) & 0xFFu], 1u);
        }
        __syncthreads();
        // warp-shuffle suffix-inclusive scan over 256 bins (warps 0..7)
        if (wid < 8) {
            const int bin = wid * 32 + lane;
            unsigned s = hist[bin];
#pragma unroll
            for (int off = 1; off < 32; off <<= 1) {
                const unsigned t = __shfl_down_sync(0xFFFFFFFFu, s, off);
                if (lane + off < 32) s += t;
            }
            hs[bin] = s;                          // suffix within warp chunk
            if (lane == 0) wsum[wid] = s;         // chunk total
        }
        __syncthreads();
        if (wid == 0 && lane < 8) {
            const unsigned v = wsum[lane];
            unsigned s = v;
#pragma unroll
            for (int off = 1; off < 8; off <<= 1) {
                const unsigned t = __shfl_down_sync(0x000000FFu, s, off);
                if (lane + off < 8) s += t;
            }
            wsum[lane] = s - v;                   // exclusive suffix of chunks
        }
        __syncthreads();
        if (tid < 256) {
            const unsigned mine = hs[tid] + wsum[tid >> 5];
            hs[tid] = mine;
        }
        __syncthreads();
        if (tid < 256) {
            const unsigned above = (tid == 255) ? 0u : hs[tid + 1];
            if (hs[tid] >= (unsigned)krem && above < (unsigned)krem) {
                sSel = (unsigned)tid; sAbove = above;
            }
        }
        __syncthreads();
        prefix |= (sSel << shift);
        hi_mask |= (0xFFu << shift);
        krem -= (int)sAbove;
        __syncthreads();
    }
    const float thr = __uint_as_float(prefix);    // truncated noisy k-th
    const float whi = thr + WCAND, wlo = thr - WCAND;

    // ---- gather boundary candidates
    for (int i = tid; i < N_FEAT; i += 512) {
        const float a = srow[i];
        if (a > whi) atomicAdd(&sA, 1);
        else if (a >= wlo) {
            const int p = atomicAdd(&sNc, 1);
            if (p < 64) s_cidx[p] = i;
        }
    }
    __syncthreads();

    const int nc = (sNc < 64) ? sNc : 64;
    const int kk = TOPK - sA;

    // ---- exact recompute, one candidate per warp (warps 0..7)
    if (wid < 8) {
        for (int c = wid; c < nc; c += 8) {
            const float4* w4 = reinterpret_cast<const float4*>(
                g_WT + (size_t)s_cidx[c] * D_IN);
            const float4* x4 = reinterpret_cast<const float4*>(xc);
#pragma unroll
            for (int s8 = 0; s8 < 8; s8++) {
                const int slab = s8 * 32 + lane;
                float part = 0.0f;
#pragma unroll
                for (int j = 0; j < 4; j++) {
                    const float4 a = x4[slab * 4 + j];
                    const float4 b = w4[slab * 4 + j];
                    part = fmaf(a.x, b.x, part);
                    part = fmaf(a.y, b.y, part);
                    part = fmaf(a.z, b.z, part);
                    part = fmaf(a.w, b.w, part);
                }
                sp[wid][slab] = part;
            }
            __syncwarp();
            if (lane == 0) {
                float acc = 0.0f;
#pragma unroll 8
                for (int j = 0; j < 256; j++) acc += sp[wid][j];  // slab order
                s_cval[c] = fmaxf(acc + be[s_cidx[c]], 0.0f);
            }
            __syncwarp();
        }
    }
    __syncthreads();

    // ---- kk-th largest exact candidate value
    if (tid < nc && kk >= 1) {
        const float v = s_cval[tid];
        int g = 0;
        for (int j = 0; j < nc; j++) g += (s_cval[j] > v);
        if (g <= kk - 1) atomicMin(&s_vbits, __float_as_uint(v));
    }
    __syncthreads();

    const bool fallback = (sNc > 64) || (kk > nc) || (kk < 1);
    const float vstar = fallback ? thr : __uint_as_float(s_vbits);

    // ---- final mask, single global write
    for (int i = tid; i < N_FEAT; i += 512) {
        const float a = srow[i];
        float o;
        if (a > whi) o = a;
        else if (a >= wlo) {
            float ex = a; bool found = false;
            for (int c = 0; c < nc; c++)
                if (s_cidx[c] == i) { ex = s_cval[c]; found = true; break; }
            if (found) o = (ex >= vstar) ? ex : 0.0f;
            else       o = (a >= thr) ? a : 0.0f;
        } else o = 0.0f;
        rowp[i] = o;
    }
}

// ---------------------------------------------------------------------------
extern "C" void kernel_launch(void* const* d_in, const int* in_sizes, int n_in,
                              void* d_out, int out_size)
{
    const float* x  = (const float*)d_in[0];
    const float* pb = (const float*)d_in[1];
    const float* W  = (const float*)d_in[2];
    const float* be = (const float*)d_in[3];
    float* out = (float*)d_out;

    cudaFuncSetAttribute(encoder_gemm_h,
                         cudaFuncAttributeMaxDynamicSharedMemorySize, SM_BYTES);

    convert_x<<<(BATCH * D_IN / 4) / 256, 256>>>(x, pb);
    prep_w<<<dim3(N_FEAT / 32, D_IN / 32), dim3(32, 8)>>>(W);
    encoder_gemm_h<<<(BATCH / GM_BM) * (N_FEAT / GM_BN), 256, SM_BYTES>>>(be, out);
    select_mask<<<BATCH, 512>>>(out, x, pb, be);
}